// round 2
// baseline (speedup 1.0000x reference)
#include <cuda_runtime.h>
#include <math.h>

#define BB 256
#define TT 512
#define FF 256
#define HH 256
#define GG 1024  /* 4*H */
#define NB 128   /* persistent CTAs */

// Scratch (device globals; no runtime allocation allowed)
__device__ float g_xw[(long long)TT * BB * GG];   // 512 MB: xW(+b), [T][B][4H]
__device__ float g_h1[(long long)TT * HH * BB];   // 128 MB: layer-1 h sequence, [T][H][B]
__device__ float g_hbuf[2 * HH * BB];             // h double buffer, [H][B]
__device__ unsigned g_cnt = 0;
__device__ unsigned g_gen = 0;

struct __align__(16) ull2 { unsigned long long x, y; };

__device__ __forceinline__ unsigned long long dupf(float v) {
    unsigned long long p;
    asm("mov.b64 %0, {%1, %1};" : "=l"(p) : "f"(v));
    return p;
}
__device__ __forceinline__ unsigned long long packf(float lo, float hi) {
    unsigned long long p;
    asm("mov.b64 %0, {%1, %2};" : "=l"(p) : "f"(lo), "f"(hi));
    return p;
}
__device__ __forceinline__ void unpackf(unsigned long long p, float& lo, float& hi) {
    asm("mov.b64 {%0, %1}, %2;" : "=f"(lo), "=f"(hi) : "l"(p));
}
__device__ __forceinline__ void ffma2(unsigned long long& d,
                                      unsigned long long a,
                                      unsigned long long b) {
    asm("fma.rn.f32x2 %0, %1, %2, %0;" : "+l"(d) : "l"(a), "l"(b));
}

__device__ __forceinline__ float sigf(float v) { return 1.0f / (1.0f + __expf(-v)); }

// ---------------------------------------------------------------------------
// Grid barrier (all NB CTAs co-resident: 128 CTAs, 1/SM on 148 SMs)
// ---------------------------------------------------------------------------
__device__ __forceinline__ void gbar() {
    __syncthreads();
    if (threadIdx.x == 0) {
        unsigned my = *((volatile unsigned*)&g_gen);
        __threadfence();
        if (atomicAdd(&g_cnt, 1) == NB - 1) {
            g_cnt = 0;
            __threadfence();
            atomicAdd(&g_gen, 1);
        } else {
            while (*((volatile unsigned*)&g_gen) == my) { }
        }
        __threadfence();
    }
    __syncthreads();
}

// ---------------------------------------------------------------------------
// GEMM: C[m][n] = sum_k A(m,k) * Bm[k][n] + bias[n]
//   M = T*B (m = t*B + b), N = 1024, K = 256. Tile 64(M) x 128(N), BK=16.
//   xmap=1: A(m,k) = x[b][t][k]   (row-contiguous in k)
//   xmap=0: A(m,k) = h1[t][k][b]  ([T][H][B]: k-rows contiguous in b)
// 256 threads, per-thread 4x8 via f32x2.
// ---------------------------------------------------------------------------
__global__ void gemm_xw_kernel(const float* __restrict__ A,
                               const float* __restrict__ Bm,
                               const float* __restrict__ bias,
                               float* __restrict__ Cout,
                               int xmap)
{
    __shared__ float As[16][72];
    __shared__ float Bs[16][128];

    const int tid = threadIdx.x;
    const int tx = tid & 15;     // n-subtile (8 cols)
    const int ty = tid >> 4;     // m-subtile (4 rows)
    const int n0 = blockIdx.x * 128;
    const int m0 = blockIdx.y * 64;

    // bias preload
    float b8[8];
    *(float4*)&b8[0] = *(const float4*)(bias + n0 + tx * 8);
    *(float4*)&b8[4] = *(const float4*)(bias + n0 + tx * 8 + 4);

    // A-load indexing
    const int lrow = tid >> 2;            // 0..63  (xmap=1)
    const int lq   = tid & 3;
    long long arow = 0;
    if (xmap) {
        const int m = m0 + lrow;
        arow = ((long long)(m & (BB - 1)) * TT + (m >> 8)) * FF;
    }
    const int h_t  = m0 >> 8;             // xmap=0
    const int h_b0 = m0 & 255;
    const int akk  = tid >> 6;            // 0..3 base k-row (4 rows of 64 floats / 256thr)
    const int acol = (tid & 63) ? (tid & 63) : 0; // not used directly; recompute below

    unsigned long long acc[4][4];
#pragma unroll
    for (int r = 0; r < 4; r++)
#pragma unroll
        for (int c = 0; c < 4; c++) acc[r][c] = 0ULL;

    for (int k0 = 0; k0 < FF; k0 += 16) {
        if (xmap) {
            float4 av = *(const float4*)(A + arow + k0 + lq * 4);
            As[lq * 4 + 0][lrow] = av.x;
            As[lq * 4 + 1][lrow] = av.y;
            As[lq * 4 + 2][lrow] = av.z;
            As[lq * 4 + 3][lrow] = av.w;
        } else {
            // 16 k-rows x 64 cols = 1024 floats, 1 float4/thread
            const int idx = tid * 4;
            const int kk = idx >> 6;          // 0..15
            const int cc = idx & 63;
            float4 av = *(const float4*)(A + (long long)h_t * HH * BB
                                           + (long long)(k0 + kk) * BB + h_b0 + cc);
            *(float4*)&As[kk][cc] = av;
        }
        // B: 16 x 128 = 2048 floats, 2 float4/thread
#pragma unroll
        for (int i = 0; i < 2; i++) {
            const int idx = (tid + i * 256) * 4;
            const int kk = idx >> 7;
            const int cc = idx & 127;
            *(float4*)&Bs[kk][cc] =
                *(const float4*)(Bm + (long long)(k0 + kk) * GG + n0 + cc);
        }
        __syncthreads();
#pragma unroll
        for (int kk = 0; kk < 16; kk++) {
            float4 a4 = *(const float4*)&As[kk][ty * 4];
            unsigned long long aa0 = dupf(a4.x);
            unsigned long long aa1 = dupf(a4.y);
            unsigned long long aa2 = dupf(a4.z);
            unsigned long long aa3 = dupf(a4.w);
            ull2 b01 = *(const ull2*)&Bs[kk][tx * 8];
            ull2 b23 = *(const ull2*)&Bs[kk][tx * 8 + 4];
            ffma2(acc[0][0], aa0, b01.x); ffma2(acc[0][1], aa0, b01.y);
            ffma2(acc[0][2], aa0, b23.x); ffma2(acc[0][3], aa0, b23.y);
            ffma2(acc[1][0], aa1, b01.x); ffma2(acc[1][1], aa1, b01.y);
            ffma2(acc[1][2], aa1, b23.x); ffma2(acc[1][3], aa1, b23.y);
            ffma2(acc[2][0], aa2, b01.x); ffma2(acc[2][1], aa2, b01.y);
            ffma2(acc[2][2], aa2, b23.x); ffma2(acc[2][3], aa2, b23.y);
            ffma2(acc[3][0], aa3, b01.x); ffma2(acc[3][1], aa3, b01.y);
            ffma2(acc[3][2], aa3, b23.x); ffma2(acc[3][3], aa3, b23.y);
        }
        __syncthreads();
    }

#pragma unroll
    for (int r = 0; r < 4; r++) {
        const int mm = m0 + ty * 4 + r;
        float out[8];
#pragma unroll
        for (int c = 0; c < 4; c++) unpackf(acc[r][c], out[2 * c], out[2 * c + 1]);
#pragma unroll
        for (int j = 0; j < 8; j++) out[j] += b8[j];
        *(float4*)&Cout[(long long)mm * GG + n0 + tx * 8]     = *(float4*)&out[0];
        *(float4*)&Cout[(long long)mm * GG + n0 + tx * 8 + 4] = *(float4*)&out[4];
    }
}

// ---------------------------------------------------------------------------
// Persistent LSTM layer: loops t = 0..T-1 with grid barrier between steps.
// Grid: 128 CTAs x 128 threads. CTA owns 16 hidden cols x 32 batch rows.
// Thread: 4 rows x 1 col x 4 gates. c kept in registers for all 512 steps.
// U cached duplicated-packed in smem (128KB); h staged per step (32KB).
// hb layout [2][H][B]; hseq layout [T][H][B].
// ---------------------------------------------------------------------------
__global__ void lstm_layer_kernel(const float* __restrict__ xw_all,  // [T][B][4H]
                                  const float* __restrict__ U,       // [H][4H]
                                  float* __restrict__ hseq,          // [T][H][B] or 0
                                  float* __restrict__ hb)            // [2][H*B]
{
    extern __shared__ char smem_raw[];
    unsigned long long* Us2 = (unsigned long long*)smem_raw;          // [k][hc][g] 128KB
    float* Hs = (float*)(smem_raw + (size_t)HH * 16 * 4 * 8);         // [k][row] 32KB

    const int tid = threadIdx.x;      // 128
    const int tx = tid & 15;          // hidden col within group
    const int ty = tid >> 4;          // 0..7 (row quad)
    const int cta = blockIdx.x;
    const int hc0 = (cta & 15) * 16;
    const int r0  = (cta >> 4) * 32;

    // One-time: cache U slice, duplicated into both f32x2 lanes.
    for (int i = tid; i < HH * 16 * 4; i += 128) {
        const int k  = i >> 6;
        const int hc = (i >> 2) & 15;
        const int g  = i & 3;
        Us2[i] = dupf(U[(long long)k * GG + g * HH + hc0 + hc]);
    }

    // Zero my slice of hb[0]; c in regs.
    float creg[4] = {0.f, 0.f, 0.f, 0.f};
    {
        float4 z = make_float4(0.f, 0.f, 0.f, 0.f);
        *(float4*)&hb[(hc0 + tx) * BB + r0 + ty * 4] = z;
    }
    gbar();

    for (int t = 0; t < TT; t++) {
        const float* hprev = hb + (t & 1) * (HH * BB);
        float* hnext = hb + ((t + 1) & 1) * (HH * BB);

        // Stage h slice: Hs[k][row] = hprev[k][r0+row], 256x32 floats.
#pragma unroll
        for (int i = 0; i < 16; i++) {
            const int idx = (tid + i * 128) * 4;
            const int k = idx >> 5;
            const int r = idx & 31;
            *(float4*)&Hs[idx] = *(const float4*)&hprev[k * BB + r0 + r];
        }

        // Init acc from precomputed xW (+bias). acc[rp][g] packs rows (2rp,2rp+1).
        const float* xw = xw_all + (long long)t * BB * GG;
        unsigned long long acc[2][4];
#pragma unroll
        for (int rp = 0; rp < 2; rp++)
#pragma unroll
            for (int g = 0; g < 4; g++) {
                const int row = r0 + ty * 4 + rp * 2;
                const float lo = xw[(long long)row * GG + g * HH + hc0 + tx];
                const float hi = xw[(long long)(row + 1) * GG + g * HH + hc0 + tx];
                acc[rp][g] = packf(lo, hi);
            }
        __syncthreads();

        const unsigned long long* Uc = Us2 + tx * 4;
#pragma unroll 8
        for (int kk = 0; kk < HH; kk++) {
            ull2 h2 = *(const ull2*)&Hs[kk * 32 + ty * 4];   // rows (0,1),(2,3)
            ull2 u01 = *(const ull2*)&Uc[kk * 64];           // gates 0,1 (dup)
            ull2 u23 = *(const ull2*)&Uc[kk * 64 + 2];       // gates 2,3 (dup)
            ffma2(acc[0][0], h2.x, u01.x); ffma2(acc[0][1], h2.x, u01.y);
            ffma2(acc[0][2], h2.x, u23.x); ffma2(acc[0][3], h2.x, u23.y);
            ffma2(acc[1][0], h2.y, u01.x); ffma2(acc[1][1], h2.y, u01.y);
            ffma2(acc[1][2], h2.y, u23.x); ffma2(acc[1][3], h2.y, u23.y);
        }

        // Gates -> c,h
        float hv[4];
#pragma unroll
        for (int rp = 0; rp < 2; rp++) {
            float zi0, zi1, zf0, zf1, zg0, zg1, zo0, zo1;
            unpackf(acc[rp][0], zi0, zi1);
            unpackf(acc[rp][1], zf0, zf1);
            unpackf(acc[rp][2], zg0, zg1);
            unpackf(acc[rp][3], zo0, zo1);
            {
                const float ig = sigf(zi0), fg = sigf(zf0);
                const float gg = __tanhf(zg0), og = sigf(zo0);
                const float cn = fg * creg[rp * 2] + ig * gg;
                creg[rp * 2] = cn;
                hv[rp * 2] = og * __tanhf(cn);
            }
            {
                const float ig = sigf(zi1), fg = sigf(zf1);
                const float gg = __tanhf(zg1), og = sigf(zo1);
                const float cn = fg * creg[rp * 2 + 1] + ig * gg;
                creg[rp * 2 + 1] = cn;
                hv[rp * 2 + 1] = og * __tanhf(cn);
            }
        }
        float4 hq = make_float4(hv[0], hv[1], hv[2], hv[3]);
        *(float4*)&hnext[(hc0 + tx) * BB + r0 + ty * 4] = hq;
        if (hseq)
            *(float4*)&hseq[(long long)t * HH * BB + (hc0 + tx) * BB + r0 + ty * 4] = hq;

        gbar();
    }
}

// ---------------------------------------------------------------------------
// out[b] = sum_k hlast[k][b] * Wd[k] + bd[0].  Grid 1 x 256 threads.
// ---------------------------------------------------------------------------
__global__ void dense_out_kernel(const float* __restrict__ hlast,  // [H][B]
                                 const float* __restrict__ Wd,
                                 const float* __restrict__ bd,
                                 float* __restrict__ out)
{
    const int b = threadIdx.x;
    float s = 0.f;
#pragma unroll 8
    for (int k = 0; k < HH; k++) s += hlast[k * BB + b] * Wd[k];
    out[b] = s + bd[0];
}

// ---------------------------------------------------------------------------
// Launch: 5 graph nodes total.
// ---------------------------------------------------------------------------
extern "C" void kernel_launch(void* const* d_in, const int* in_sizes, int n_in,
                              void* d_out, int out_size)
{
    const float* x  = (const float*)d_in[0];
    const float* W1 = (const float*)d_in[1];
    const float* U1 = (const float*)d_in[2];
    const float* b1 = (const float*)d_in[3];
    const float* W2 = (const float*)d_in[4];
    const float* U2 = (const float*)d_in[5];
    const float* b2 = (const float*)d_in[6];
    const float* Wd = (const float*)d_in[7];
    const float* bd = (const float*)d_in[8];
    float* out = (float*)d_out;

    float *xw, *h1, *hbuf;
    cudaGetSymbolAddress((void**)&xw, g_xw);
    cudaGetSymbolAddress((void**)&h1, g_h1);
    cudaGetSymbolAddress((void**)&hbuf, g_hbuf);

    const int lstm_smem = HH * 16 * 4 * 8 + HH * 32 * 4;  // 128KB + 32KB
    cudaFuncSetAttribute(lstm_layer_kernel,
                         cudaFuncAttributeMaxDynamicSharedMemorySize, lstm_smem);

    const dim3 gemm_grid(GG / 128, (TT * BB) / 64);

    // Layer 1
    gemm_xw_kernel<<<gemm_grid, 256>>>(x, W1, b1, xw, 1);
    lstm_layer_kernel<<<NB, 128, lstm_smem>>>(xw, U1, h1, hbuf);

    // Layer 2
    gemm_xw_kernel<<<gemm_grid, 256>>>(h1, W2, b2, xw, 0);
    lstm_layer_kernel<<<NB, 128, lstm_smem>>>(xw, U2, (float*)0, hbuf);

    // Dense head: final h is in buffer 0 (T even).
    dense_out_kernel<<<1, 256>>>(hbuf, Wd, bd, out);
}

// round 3
// speedup vs baseline: 1.1939x; 1.1939x over previous
#include <cuda_runtime.h>
#include <math.h>

#define BB 256
#define TT 512
#define FF 256
#define HH 256
#define GG 1024   /* 4*H */
#define NB 128    /* persistent CTAs */
#define HSTRIDE 34 /* ull stride per k-row in Hs2 (bank padding) */

typedef unsigned long long ull;
struct __align__(16) ull2 { ull x, y; };

// Scratch (device globals; no runtime allocation allowed)
__device__ float g_xw[(size_t)TT * GG * BB];   // 512 MB: xW(+b), [T][4H][B]
__device__ float g_h1[(size_t)TT * HH * BB];   // 128 MB: layer-1 h, [T][H][B]
__device__ float g_hbuf[2 * HH * BB];          // h double buffer, [2][H][B]
__device__ unsigned g_cnt;
__device__ unsigned g_gen;

__device__ __forceinline__ ull dupf(float v) {
    ull p; asm("mov.b64 %0, {%1, %1};" : "=l"(p) : "f"(v)); return p;
}
__device__ __forceinline__ ull packf(float lo, float hi) {
    ull p; asm("mov.b64 %0, {%1, %2};" : "=l"(p) : "f"(lo), "f"(hi)); return p;
}
__device__ __forceinline__ void unpackf(ull p, float& lo, float& hi) {
    asm("mov.b64 {%0, %1}, %2;" : "=f"(lo), "=f"(hi) : "l"(p));
}
__device__ __forceinline__ void ffma2(ull& d, ull a, ull b) {
    asm("fma.rn.f32x2 %0, %1, %2, %0;" : "+l"(d) : "l"(a), "l"(b));
}
__device__ __forceinline__ float sigf(float v) { return 1.0f / (1.0f + __expf(-v)); }

// ---------------------------------------------------------------------------
// Split grid barrier: cumulative count, release/acquire semantics.
// target T: arrive increments; releaser (old == NB*T-1) publishes g_gen = T.
// ---------------------------------------------------------------------------
__device__ __forceinline__ void bar_arrive(unsigned target) {
    __syncthreads();
    if (threadIdx.x == 0) {
        unsigned old;
        asm volatile("atom.add.release.gpu.u32 %0, [%1], 1;"
                     : "=r"(old) : "l"(&g_cnt) : "memory");
        if (old == NB * target - 1) {
            asm volatile("st.release.gpu.u32 [%0], %1;"
                         :: "l"(&g_gen), "r"(target) : "memory");
        }
    }
}
__device__ __forceinline__ void bar_wait(unsigned target) {
    if (threadIdx.x == 0) {
        unsigned g;
        do {
            asm volatile("ld.acquire.gpu.u32 %0, [%1];"
                         : "=r"(g) : "l"(&g_gen) : "memory");
        } while (g < target);
    }
    __syncthreads();
}

// ---------------------------------------------------------------------------
// Reset barrier state + zero h0 buffer (before each LSTM layer)
// ---------------------------------------------------------------------------
__global__ void init_state_kernel() {
    int i = blockIdx.x * blockDim.x + threadIdx.x;
    if (i < HH * BB) g_hbuf[i] = 0.0f;
    if (i == 0) { g_cnt = 0; g_gen = 0; }
}

// ---------------------------------------------------------------------------
// GEMM: Cout[t][n][b] = sum_k A(m,k) * Bm[k][n] + bias[n],  m = t*B + b
//   xmap=1: A(m,k) = x[b][t][k];  xmap=0: A(m,k) = h1[t][k][b]
// Tile 64(M) x 128(N), BK=16, 256 threads, per-thread 4x8 via f32x2.
// Output written TRANSPOSED: [T][4H][B].
// ---------------------------------------------------------------------------
__global__ void gemm_xw_kernel(const float* __restrict__ A,
                               const float* __restrict__ Bm,
                               const float* __restrict__ bias,
                               float* __restrict__ Cout,
                               int xmap)
{
    __shared__ float As[16][72];
    __shared__ float Bs[16][128];

    const int tid = threadIdx.x;
    const int tx = tid & 15;     // n-subtile (8 cols)
    const int ty = tid >> 4;     // m-subtile (4 rows)
    const int n0 = blockIdx.x * 128;
    const int m0 = blockIdx.y * 64;

    float b8[8];
    *(float4*)&b8[0] = *(const float4*)(bias + n0 + tx * 8);
    *(float4*)&b8[4] = *(const float4*)(bias + n0 + tx * 8 + 4);

    const int lrow = tid >> 2;
    const int lq   = tid & 3;
    long long arow = 0;
    if (xmap) {
        const int m = m0 + lrow;
        arow = ((long long)(m & (BB - 1)) * TT + (m >> 8)) * FF;
    }
    const int h_t  = m0 >> 8;
    const int h_b0 = m0 & 255;

    ull acc[4][4];
#pragma unroll
    for (int r = 0; r < 4; r++)
#pragma unroll
        for (int c = 0; c < 4; c++) acc[r][c] = 0ULL;

    for (int k0 = 0; k0 < FF; k0 += 16) {
        if (xmap) {
            float4 av = *(const float4*)(A + arow + k0 + lq * 4);
            As[lq * 4 + 0][lrow] = av.x;
            As[lq * 4 + 1][lrow] = av.y;
            As[lq * 4 + 2][lrow] = av.z;
            As[lq * 4 + 3][lrow] = av.w;
        } else {
            const int idx = tid * 4;
            const int kk = idx >> 6;
            const int cc = idx & 63;
            float4 av = *(const float4*)(A + (size_t)h_t * HH * BB
                                           + (size_t)(k0 + kk) * BB + h_b0 + cc);
            *(float4*)&As[kk][cc] = av;
        }
#pragma unroll
        for (int i = 0; i < 2; i++) {
            const int idx = (tid + i * 256) * 4;
            const int kk = idx >> 7;
            const int cc = idx & 127;
            *(float4*)&Bs[kk][cc] =
                *(const float4*)(Bm + (size_t)(k0 + kk) * GG + n0 + cc);
        }
        __syncthreads();
#pragma unroll
        for (int kk = 0; kk < 16; kk++) {
            float4 a4 = *(const float4*)&As[kk][ty * 4];
            ull aa0 = dupf(a4.x), aa1 = dupf(a4.y);
            ull aa2 = dupf(a4.z), aa3 = dupf(a4.w);
            ull2 b01 = *(const ull2*)&Bs[kk][tx * 8];
            ull2 b23 = *(const ull2*)&Bs[kk][tx * 8 + 4];
            ffma2(acc[0][0], aa0, b01.x); ffma2(acc[0][1], aa0, b01.y);
            ffma2(acc[0][2], aa0, b23.x); ffma2(acc[0][3], aa0, b23.y);
            ffma2(acc[1][0], aa1, b01.x); ffma2(acc[1][1], aa1, b01.y);
            ffma2(acc[1][2], aa1, b23.x); ffma2(acc[1][3], aa1, b23.y);
            ffma2(acc[2][0], aa2, b01.x); ffma2(acc[2][1], aa2, b01.y);
            ffma2(acc[2][2], aa2, b23.x); ffma2(acc[2][3], aa2, b23.y);
            ffma2(acc[3][0], aa3, b01.x); ffma2(acc[3][1], aa3, b01.y);
            ffma2(acc[3][2], aa3, b23.x); ffma2(acc[3][3], aa3, b23.y);
        }
        __syncthreads();
    }

    // Transposed write: Cout[t][n][b], per-column float4 over 4 consecutive b.
    float o[4][8];
#pragma unroll
    for (int r = 0; r < 4; r++) {
#pragma unroll
        for (int c = 0; c < 4; c++) unpackf(acc[r][c], o[r][2 * c], o[r][2 * c + 1]);
#pragma unroll
        for (int j = 0; j < 8; j++) o[r][j] += b8[j];
    }
    const int t_out = m0 >> 8;
    const int b_out = (m0 & 255) + ty * 4;
    float* cb = Cout + (size_t)t_out * GG * BB + (size_t)(n0 + tx * 8) * BB + b_out;
#pragma unroll
    for (int j = 0; j < 8; j++) {
        float4 v = make_float4(o[0][j], o[1][j], o[2][j], o[3][j]);
        *(float4*)(cb + (size_t)j * BB) = v;
    }
}

// ---------------------------------------------------------------------------
// Persistent LSTM layer. 128 CTAs x 128 threads; CTA owns 16 hc x 32 rows.
// Thread: 1 hc x 4 rows; acc packs GATE pairs (i,f),(g,o) in f32x2 lanes.
// U in smem as packed pairs (64KB); h staged lane-duplicated (68KB).
// xw prefetched into regs between bar_arrive and bar_wait.
// ---------------------------------------------------------------------------
__global__ void lstm_layer_kernel(const float* __restrict__ xw_all,  // [T][4H][B]
                                  const float* __restrict__ U,       // [H][4H]
                                  float* __restrict__ hseq,          // [T][H][B] or 0
                                  float* __restrict__ hb)            // [2][H*B]
{
    extern __shared__ ull smem[];
    ull* Us  = smem;                 // [k][hc][pair]: (k*16+hc)*2 + p   (64KB)
    ull* Hs2 = smem + HH * 16 * 2;   // [k][row] dup'd, stride HSTRIDE   (68KB)

    const int tid = threadIdx.x;
    const int tx = tid & 15;
    const int ty = tid >> 4;         // 0..7
    const int hc0 = (blockIdx.x & 15) * 16;
    const int r0  = (blockIdx.x >> 4) * 32;

    // One-time U cache: pairs (i,f) and (g,o).
    for (int i = tid; i < HH * 16; i += 128) {
        const int k = i >> 4, hc = i & 15;
        const float* up = U + (size_t)k * GG + hc0 + hc;
        Us[i * 2 + 0] = packf(up[0 * HH], up[1 * HH]);
        Us[i * 2 + 1] = packf(up[2 * HH], up[3 * HH]);
    }

    float creg[4] = {0.f, 0.f, 0.f, 0.f};

    // Prefetch xw for t=0.
    float4 xp[4];
    {
        const float* xwt = xw_all;
#pragma unroll
        for (int g = 0; g < 4; g++)
            xp[g] = *(const float4*)(xwt + (size_t)(g * HH + hc0 + tx) * BB + r0 + ty * 4);
    }

    const ull* Up = Us + tx * 2;
    const ull* Hp = Hs2 + ty * 4;

    for (int t = 0; t < TT; t++) {
        if (t) bar_wait((unsigned)t);
        const float* hprev = hb + (t & 1) * (HH * BB);
        float* hnext = hb + ((t + 1) & 1) * (HH * BB);

        // Stage h (lane-duplicated): Hs2[k*HSTRIDE + r] = dup(hprev[k][r0+r]).
#pragma unroll
        for (int j = 0; j < 16; j++) {
            const int k = j * 16 + (tid >> 3);
            const int rr = (tid & 7) * 4;
            float4 hv = *(const float4*)&hprev[k * BB + r0 + rr];
            ull* dst = &Hs2[k * HSTRIDE + rr];
            dst[0] = dupf(hv.x); dst[1] = dupf(hv.y);
            dst[2] = dupf(hv.z); dst[3] = dupf(hv.w);
        }

        // acc[r] = (zi,zf),(zg,zo) initialized from prefetched xW.
        float xa[4][4];
#pragma unroll
        for (int g = 0; g < 4; g++) *(float4*)xa[g] = xp[g];
        ull acc[4][2];
#pragma unroll
        for (int r = 0; r < 4; r++) {
            acc[r][0] = packf(xa[0][r], xa[1][r]);
            acc[r][1] = packf(xa[2][r], xa[3][r]);
        }
        __syncthreads();

#pragma unroll 8
        for (int kk = 0; kk < HH; kk++) {
            ull2 u  = *(const ull2*)(Up + kk * 32);
            ull2 ha = *(const ull2*)(Hp + kk * HSTRIDE);
            ull2 hc = *(const ull2*)(Hp + kk * HSTRIDE + 2);
            ffma2(acc[0][0], ha.x, u.x); ffma2(acc[0][1], ha.x, u.y);
            ffma2(acc[1][0], ha.y, u.x); ffma2(acc[1][1], ha.y, u.y);
            ffma2(acc[2][0], hc.x, u.x); ffma2(acc[2][1], hc.x, u.y);
            ffma2(acc[3][0], hc.y, u.x); ffma2(acc[3][1], hc.y, u.y);
        }

        // Gates -> c,h
        float hv[4];
#pragma unroll
        for (int r = 0; r < 4; r++) {
            float zi, zf, zg, zo;
            unpackf(acc[r][0], zi, zf);
            unpackf(acc[r][1], zg, zo);
            const float ig = sigf(zi), fg = sigf(zf);
            const float gg = __tanhf(zg), og = sigf(zo);
            const float cn = fg * creg[r] + ig * gg;
            creg[r] = cn;
            hv[r] = og * __tanhf(cn);
        }
        float4 hq = make_float4(hv[0], hv[1], hv[2], hv[3]);
        *(float4*)&hnext[(hc0 + tx) * BB + r0 + ty * 4] = hq;
        if (hseq)
            *(float4*)&hseq[(size_t)t * HH * BB + (hc0 + tx) * BB + r0 + ty * 4] = hq;

        bar_arrive((unsigned)(t + 1));

        // Prefetch next step's xw while other CTAs finish (hides DRAM latency).
        const int tn = (t + 1 < TT) ? (t + 1) : t;
        const float* xwt = xw_all + (size_t)tn * GG * BB;
#pragma unroll
        for (int g = 0; g < 4; g++)
            xp[g] = *(const float4*)(xwt + (size_t)(g * HH + hc0 + tx) * BB + r0 + ty * 4);
    }
}

// ---------------------------------------------------------------------------
// out[b] = sum_k hlast[k][b] * Wd[k] + bd[0]
// ---------------------------------------------------------------------------
__global__ void dense_out_kernel(const float* __restrict__ hlast,  // [H][B]
                                 const float* __restrict__ Wd,
                                 const float* __restrict__ bd,
                                 float* __restrict__ out)
{
    const int b = threadIdx.x;
    float s = 0.f;
#pragma unroll 8
    for (int k = 0; k < HH; k++) s += hlast[k * BB + b] * Wd[k];
    out[b] = s + bd[0];
}

// ---------------------------------------------------------------------------
// Launch: 7 graph nodes.
// ---------------------------------------------------------------------------
extern "C" void kernel_launch(void* const* d_in, const int* in_sizes, int n_in,
                              void* d_out, int out_size)
{
    const float* x  = (const float*)d_in[0];
    const float* W1 = (const float*)d_in[1];
    const float* U1 = (const float*)d_in[2];
    const float* b1 = (const float*)d_in[3];
    const float* W2 = (const float*)d_in[4];
    const float* U2 = (const float*)d_in[5];
    const float* b2 = (const float*)d_in[6];
    const float* Wd = (const float*)d_in[7];
    const float* bd = (const float*)d_in[8];
    float* out = (float*)d_out;

    float *xw, *h1, *hbuf;
    cudaGetSymbolAddress((void**)&xw, g_xw);
    cudaGetSymbolAddress((void**)&h1, g_h1);
    cudaGetSymbolAddress((void**)&hbuf, g_hbuf);

    const int lstm_smem = (HH * 16 * 2 + HH * HSTRIDE) * 8;  // 64KB + 68KB
    cudaFuncSetAttribute(lstm_layer_kernel,
                         cudaFuncAttributeMaxDynamicSharedMemorySize, lstm_smem);

    const dim3 gemm_grid(GG / 128, (TT * BB) / 64);

    // Layer 1
    gemm_xw_kernel<<<gemm_grid, 256>>>(x, W1, b1, xw, 1);
    init_state_kernel<<<(HH * BB + 255) / 256, 256>>>();
    lstm_layer_kernel<<<NB, 128, lstm_smem>>>(xw, U1, h1, hbuf);

    // Layer 2
    gemm_xw_kernel<<<gemm_grid, 256>>>(h1, W2, b2, xw, 0);
    init_state_kernel<<<(HH * BB + 255) / 256, 256>>>();
    lstm_layer_kernel<<<NB, 128, lstm_smem>>>(xw, U2, (float*)0, hbuf);

    // Dense head: final h in buffer 0 (T even).
    dense_out_kernel<<<1, 256>>>(hbuf, Wd, bd, out);
}

// round 4
// speedup vs baseline: 1.4038x; 1.1758x over previous
#include <cuda_runtime.h>
#include <math.h>

#define BB 256
#define TT 512
#define FF 256
#define HH 256
#define GG 1024    /* 4*H */
#define NB 128     /* persistent CTAs */
#define HSTRIDE 34 /* ull stride per k-row in Hs2 (bank padding) */
#define ASTRIDE 130 /* ull stride per k-row in AsD */

typedef unsigned long long ull;
struct __align__(16) ull2 { ull x, y; };

// Scratch (device globals; no runtime allocation allowed)
__device__ float g_xw[(size_t)TT * GG * BB];   // 512 MB: xW(+b), [T][4H][B]
__device__ float g_h1[(size_t)TT * HH * BB];   // 128 MB: layer-1 h, [T][H][B]
__device__ float g_hbuf[2 * HH * BB];          // h double buffer, [2][H][B]
__device__ unsigned g_cnt;
__device__ unsigned g_gen;

__device__ __forceinline__ ull dupf(float v) {
    ull p; asm("mov.b64 %0, {%1, %1};" : "=l"(p) : "f"(v)); return p;
}
__device__ __forceinline__ ull packf(float lo, float hi) {
    ull p; asm("mov.b64 %0, {%1, %2};" : "=l"(p) : "f"(lo), "f"(hi)); return p;
}
__device__ __forceinline__ void unpackf(ull p, float& lo, float& hi) {
    asm("mov.b64 {%0, %1}, %2;" : "=f"(lo), "=f"(hi) : "l"(p));
}
__device__ __forceinline__ void ffma2(ull& d, ull a, ull b) {
    asm("fma.rn.f32x2 %0, %1, %2, %0;" : "+l"(d) : "l"(a), "l"(b));
}
__device__ __forceinline__ float sigf(float v) { return 1.0f / (1.0f + __expf(-v)); }

// ---------------------------------------------------------------------------
// Split grid barrier: cumulative count, release/acquire.
// ---------------------------------------------------------------------------
__device__ __forceinline__ void bar_arrive(unsigned target) {
    __syncthreads();
    if (threadIdx.x == 0) {
        unsigned old;
        asm volatile("atom.add.release.gpu.u32 %0, [%1], 1;"
                     : "=r"(old) : "l"(&g_cnt) : "memory");
        if (old == NB * target - 1) {
            asm volatile("st.release.gpu.u32 [%0], %1;"
                         :: "l"(&g_gen), "r"(target) : "memory");
        }
    }
}
__device__ __forceinline__ void bar_wait(unsigned target) {
    if (threadIdx.x == 0) {
        unsigned g;
        do {
            asm volatile("ld.acquire.gpu.u32 %0, [%1];"
                         : "=r"(g) : "l"(&g_gen) : "memory");
        } while (g < target);
    }
    __syncthreads();
}

// ---------------------------------------------------------------------------
// Reset barrier state + zero h0 buffer (before each LSTM layer)
// ---------------------------------------------------------------------------
__global__ void init_state_kernel() {
    int i = blockIdx.x * blockDim.x + threadIdx.x;
    if (i < HH * BB) g_hbuf[i] = 0.0f;
    if (i == 0) { g_cnt = 0; g_gen = 0; }
}

// ---------------------------------------------------------------------------
// GEMM: Cout[t][n][b] = sum_k A(m,k) * Bm[k][n] + bias[n],  m = t*B + b
//   xmap=1: A(m,k) = x[b][t][k];  xmap=0: A(m,k) = h1[t][k][b]
// Tile 128(M) x 128(N), BK=16, 256 threads, per-thread 8x8 via f32x2.
// A cached lane-duplicated (ull) in smem -> inner loop has no MOV dups.
// Output written TRANSPOSED: [T][4H][B].
// ---------------------------------------------------------------------------
__global__ void __launch_bounds__(256, 2)
gemm_xw_kernel(const float* __restrict__ A,
               const float* __restrict__ Bm,
               const float* __restrict__ bias,
               float* __restrict__ Cout,
               int xmap)
{
    __shared__ ull AsD[16 * ASTRIDE];    // [k][row] dup'd
    __shared__ float Bs[16][128];

    const int tid = threadIdx.x;
    const int tx = tid & 15;     // n-subtile (8 cols at tx*8)
    const int ty = tid >> 4;     // m-subtile (8 rows at ty*8)
    const int n0 = blockIdx.x * 128;
    const int m0 = blockIdx.y * 128;
    const int t_out = m0 >> 8;
    const int b0 = m0 & 255;

    float b8[8];
    *(float4*)&b8[0] = *(const float4*)(bias + n0 + tx * 8);
    *(float4*)&b8[4] = *(const float4*)(bias + n0 + tx * 8 + 4);

    // A-load indexing (xmap=1): thread -> (row, k-half)
    const int lrow = tid >> 1;          // 0..127
    const int lkh  = tid & 1;           // 0..1 (k offset 0 or 8)
    long long arow = 0;
    if (xmap)
        arow = ((long long)(b0 + lrow) * TT + t_out) * FF;
    // A-load indexing (xmap=0): thread -> (kk, 8 cols)
    const int hkk = tid >> 4;
    const int hc0 = (tid & 15) * 8;

    ull acc[8][4];
#pragma unroll
    for (int r = 0; r < 8; r++)
#pragma unroll
        for (int c = 0; c < 4; c++) acc[r][c] = 0ULL;

    for (int k0 = 0; k0 < FF; k0 += 16) {
        if (xmap) {
            float4 a0 = *(const float4*)(A + arow + k0 + lkh * 8);
            float4 a1 = *(const float4*)(A + arow + k0 + lkh * 8 + 4);
            const int kb = lkh * 8;
            AsD[(kb + 0) * ASTRIDE + lrow] = dupf(a0.x);
            AsD[(kb + 1) * ASTRIDE + lrow] = dupf(a0.y);
            AsD[(kb + 2) * ASTRIDE + lrow] = dupf(a0.z);
            AsD[(kb + 3) * ASTRIDE + lrow] = dupf(a0.w);
            AsD[(kb + 4) * ASTRIDE + lrow] = dupf(a1.x);
            AsD[(kb + 5) * ASTRIDE + lrow] = dupf(a1.y);
            AsD[(kb + 6) * ASTRIDE + lrow] = dupf(a1.z);
            AsD[(kb + 7) * ASTRIDE + lrow] = dupf(a1.w);
        } else {
            const float* src = A + (size_t)t_out * HH * BB
                                 + (size_t)(k0 + hkk) * BB + b0 + hc0;
            float4 a0 = *(const float4*)(src);
            float4 a1 = *(const float4*)(src + 4);
            ull* dst = &AsD[hkk * ASTRIDE + hc0];
            ull2 d; 
            d.x = dupf(a0.x); d.y = dupf(a0.y); *(ull2*)(dst + 0) = d;
            d.x = dupf(a0.z); d.y = dupf(a0.w); *(ull2*)(dst + 2) = d;
            d.x = dupf(a1.x); d.y = dupf(a1.y); *(ull2*)(dst + 4) = d;
            d.x = dupf(a1.z); d.y = dupf(a1.w); *(ull2*)(dst + 6) = d;
        }
#pragma unroll
        for (int i = 0; i < 2; i++) {
            const int idx = (tid + i * 256) * 4;
            const int kk = idx >> 7;
            const int cc = idx & 127;
            *(float4*)&Bs[kk][cc] =
                *(const float4*)(Bm + (size_t)(k0 + kk) * GG + n0 + cc);
        }
        __syncthreads();
#pragma unroll
        for (int kk = 0; kk < 16; kk++) {
            const ull* ar = &AsD[kk * ASTRIDE + ty * 8];
            ull2 a01 = *(const ull2*)(ar + 0);
            ull2 a23 = *(const ull2*)(ar + 2);
            ull2 a45 = *(const ull2*)(ar + 4);
            ull2 a67 = *(const ull2*)(ar + 6);
            ull2 b01 = *(const ull2*)&Bs[kk][tx * 8];
            ull2 b23 = *(const ull2*)&Bs[kk][tx * 8 + 4];
            ffma2(acc[0][0], a01.x, b01.x); ffma2(acc[0][1], a01.x, b01.y);
            ffma2(acc[0][2], a01.x, b23.x); ffma2(acc[0][3], a01.x, b23.y);
            ffma2(acc[1][0], a01.y, b01.x); ffma2(acc[1][1], a01.y, b01.y);
            ffma2(acc[1][2], a01.y, b23.x); ffma2(acc[1][3], a01.y, b23.y);
            ffma2(acc[2][0], a23.x, b01.x); ffma2(acc[2][1], a23.x, b01.y);
            ffma2(acc[2][2], a23.x, b23.x); ffma2(acc[2][3], a23.x, b23.y);
            ffma2(acc[3][0], a23.y, b01.x); ffma2(acc[3][1], a23.y, b01.y);
            ffma2(acc[3][2], a23.y, b23.x); ffma2(acc[3][3], a23.y, b23.y);
            ffma2(acc[4][0], a45.x, b01.x); ffma2(acc[4][1], a45.x, b01.y);
            ffma2(acc[4][2], a45.x, b23.x); ffma2(acc[4][3], a45.x, b23.y);
            ffma2(acc[5][0], a45.y, b01.x); ffma2(acc[5][1], a45.y, b01.y);
            ffma2(acc[5][2], a45.y, b23.x); ffma2(acc[5][3], a45.y, b23.y);
            ffma2(acc[6][0], a67.x, b01.x); ffma2(acc[6][1], a67.x, b01.y);
            ffma2(acc[6][2], a67.x, b23.x); ffma2(acc[6][3], a67.x, b23.y);
            ffma2(acc[7][0], a67.y, b01.x); ffma2(acc[7][1], a67.y, b01.y);
            ffma2(acc[7][2], a67.y, b23.x); ffma2(acc[7][3], a67.y, b23.y);
        }
        __syncthreads();
    }

    // Transposed write: Cout[t][n][b]
    float o[8][8];
#pragma unroll
    for (int r = 0; r < 8; r++) {
#pragma unroll
        for (int c = 0; c < 4; c++) unpackf(acc[r][c], o[r][2 * c], o[r][2 * c + 1]);
#pragma unroll
        for (int j = 0; j < 8; j++) o[r][j] += b8[j];
    }
    float* cb = Cout + (size_t)t_out * GG * BB
                     + (size_t)(n0 + tx * 8) * BB + b0 + ty * 8;
#pragma unroll
    for (int j = 0; j < 8; j++) {
        float4 v0 = make_float4(o[0][j], o[1][j], o[2][j], o[3][j]);
        float4 v1 = make_float4(o[4][j], o[5][j], o[6][j], o[7][j]);
        *(float4*)(cb + (size_t)j * BB)     = v0;
        *(float4*)(cb + (size_t)j * BB + 4) = v1;
    }
}

// ---------------------------------------------------------------------------
// Persistent LSTM layer. 128 CTAs x 256 threads (2 warps/SMSP).
// CTA owns 16 hc x 32 rows; thread owns 2 rows x 1 hc x 4 gates.
// acc packs gate pairs (i,f),(g,o) in f32x2 lanes; c in regs for all T steps.
// U pair-packed in smem (64KB); h staged lane-duplicated (70KB).
// xw prefetched into regs between bar_arrive and bar_wait.
// ---------------------------------------------------------------------------
__global__ void __launch_bounds__(256, 1)
lstm_layer_kernel(const float* __restrict__ xw_all,  // [T][4H][B]
                  const float* __restrict__ U,       // [H][4H]
                  float* __restrict__ hseq,          // [T][H][B] or 0
                  float* __restrict__ hb)            // [2][H*B]
{
    extern __shared__ ull smem[];
    ull* Us  = smem;                 // [k][hc][pair]: (k*16+hc)*2 + p  (64KB)
    ull* Hs2 = smem + HH * 16 * 2;   // [k][row] dup'd, stride HSTRIDE  (~70KB)

    const int tid = threadIdx.x;
    const int tx = tid & 15;          // hc within group
    const int ty = tid >> 4;          // 0..15 (row pair)
    const int w  = tid >> 5;          // warp 0..7
    const int lane = tid & 31;
    const int hc0 = (blockIdx.x & 15) * 16;
    const int r0  = (blockIdx.x >> 4) * 32;

    // One-time U cache: pairs (i,f) and (g,o).
    for (int i = tid; i < HH * 16; i += 256) {
        const int k = i >> 4, hc = i & 15;
        const float* up = U + (size_t)k * GG + hc0 + hc;
        Us[i * 2 + 0] = packf(up[0 * HH], up[1 * HH]);
        Us[i * 2 + 1] = packf(up[2 * HH], up[3 * HH]);
    }

    float creg[2] = {0.f, 0.f};

    // Prefetch xw for t=0 (4 gates x float2 for my 2 rows).
    float2 xp[4];
#pragma unroll
    for (int g = 0; g < 4; g++)
        xp[g] = *(const float2*)(xw_all + (size_t)(g * HH + hc0 + tx) * BB
                                         + r0 + ty * 2);

    const ull* Up = Us + tx * 2;
    const ull* Hp = Hs2 + ty * 2;
    const int sk = w * 32 + (lane >> 3);   // staging k base
    const int sc = (lane & 7) * 4;         // staging col

    for (int t = 0; t < TT; t++) {
        if (t) bar_wait((unsigned)t);
        const float* hprev = hb + (t & 1) * (HH * BB);
        float* hnext = hb + ((t + 1) & 1) * (HH * BB);

        // Stage h lane-duplicated: Hs2[k*HSTRIDE + r] = dup(hprev[k][r0+r]).
#pragma unroll
        for (int j = 0; j < 8; j++) {
            const int k = sk + j * 4;
            float4 hv = *(const float4*)&hprev[k * BB + r0 + sc];
            ull* dst = &Hs2[k * HSTRIDE + sc];
            ull2 d;
            d.x = dupf(hv.x); d.y = dupf(hv.y); *(ull2*)(dst + 0) = d;
            d.x = dupf(hv.z); d.y = dupf(hv.w); *(ull2*)(dst + 2) = d;
        }

        // acc[r] = (zi,zf),(zg,zo) from prefetched xW.
        ull acc[2][2];
        acc[0][0] = packf(xp[0].x, xp[1].x);
        acc[0][1] = packf(xp[2].x, xp[3].x);
        acc[1][0] = packf(xp[0].y, xp[1].y);
        acc[1][1] = packf(xp[2].y, xp[3].y);
        __syncthreads();

#pragma unroll 16
        for (int kk = 0; kk < HH; kk++) {
            ull2 u  = *(const ull2*)(Up + kk * 32);
            ull2 hd = *(const ull2*)(Hp + kk * HSTRIDE);
            ffma2(acc[0][0], hd.x, u.x); ffma2(acc[0][1], hd.x, u.y);
            ffma2(acc[1][0], hd.y, u.x); ffma2(acc[1][1], hd.y, u.y);
        }

        // Gates -> c,h
        float hv[2];
#pragma unroll
        for (int r = 0; r < 2; r++) {
            float zi, zf, zg, zo;
            unpackf(acc[r][0], zi, zf);
            unpackf(acc[r][1], zg, zo);
            const float ig = sigf(zi), fg = sigf(zf);
            const float gg = __tanhf(zg), og = sigf(zo);
            const float cn = fg * creg[r] + ig * gg;
            creg[r] = cn;
            hv[r] = og * __tanhf(cn);
        }
        float2 hq = make_float2(hv[0], hv[1]);
        *(float2*)&hnext[(hc0 + tx) * BB + r0 + ty * 2] = hq;
        if (hseq)
            *(float2*)&hseq[(size_t)t * HH * BB + (hc0 + tx) * BB + r0 + ty * 2] = hq;

        bar_arrive((unsigned)(t + 1));

        // Prefetch next step's xw while other CTAs finish.
        const int tn = (t + 1 < TT) ? (t + 1) : t;
        const float* xwt = xw_all + (size_t)tn * GG * BB;
#pragma unroll
        for (int g = 0; g < 4; g++)
            xp[g] = *(const float2*)(xwt + (size_t)(g * HH + hc0 + tx) * BB
                                         + r0 + ty * 2);
    }
}

// ---------------------------------------------------------------------------
// out[b] = sum_k hlast[k][b] * Wd[k] + bd[0]
// ---------------------------------------------------------------------------
__global__ void dense_out_kernel(const float* __restrict__ hlast,  // [H][B]
                                 const float* __restrict__ Wd,
                                 const float* __restrict__ bd,
                                 float* __restrict__ out)
{
    const int b = threadIdx.x;
    float s = 0.f;
#pragma unroll 8
    for (int k = 0; k < HH; k++) s += hlast[k * BB + b] * Wd[k];
    out[b] = s + bd[0];
}

// ---------------------------------------------------------------------------
// Launch: 7 graph nodes.
// ---------------------------------------------------------------------------
extern "C" void kernel_launch(void* const* d_in, const int* in_sizes, int n_in,
                              void* d_out, int out_size)
{
    const float* x  = (const float*)d_in[0];
    const float* W1 = (const float*)d_in[1];
    const float* U1 = (const float*)d_in[2];
    const float* b1 = (const float*)d_in[3];
    const float* W2 = (const float*)d_in[4];
    const float* U2 = (const float*)d_in[5];
    const float* b2 = (const float*)d_in[6];
    const float* Wd = (const float*)d_in[7];
    const float* bd = (const float*)d_in[8];
    float* out = (float*)d_out;

    float *xw, *h1, *hbuf;
    cudaGetSymbolAddress((void**)&xw, g_xw);
    cudaGetSymbolAddress((void**)&h1, g_h1);
    cudaGetSymbolAddress((void**)&hbuf, g_hbuf);

    const int lstm_smem = (HH * 16 * 2 + HH * HSTRIDE) * 8;  // 64KB + ~70KB
    cudaFuncSetAttribute(lstm_layer_kernel,
                         cudaFuncAttributeMaxDynamicSharedMemorySize, lstm_smem);

    const dim3 gemm_grid(GG / 128, (TT * BB) / 128);

    // Layer 1
    gemm_xw_kernel<<<gemm_grid, 256>>>(x, W1, b1, xw, 1);
    init_state_kernel<<<(HH * BB + 255) / 256, 256>>>();
    lstm_layer_kernel<<<NB, 256, lstm_smem>>>(xw, U1, h1, hbuf);

    // Layer 2
    gemm_xw_kernel<<<gemm_grid, 256>>>(h1, W2, b2, xw, 0);
    init_state_kernel<<<(HH * BB + 255) / 256, 256>>>();
    lstm_layer_kernel<<<NB, 256, lstm_smem>>>(xw, U2, (float*)0, hbuf);

    // Dense head: final h in buffer 0 (T even).
    dense_out_kernel<<<1, 256>>>(hbuf, Wd, bd, out);
}

// round 6
// speedup vs baseline: 2.1771x; 1.5509x over previous
#include <cuda_runtime.h>
#include <cuda_bf16.h>
#include <math.h>
#include <stdint.h>

#define BB 256
#define TT 512
#define FF 256
#define HH 256
#define GG 1024     /* 4*H */
#define NB 128      /* persistent CTAs */
#define ASTRIDE 130 /* ull stride per k-row in GEMM AsD */

typedef unsigned long long ull;
struct __align__(16) ull2 { ull x, y; };

// ---------------- device globals (no runtime allocation) --------------------
__device__ float g_xw[(size_t)TT * BB * GG];     // 512 MB: xW(+b), [T][B][4H]
__device__ float g_h1[(size_t)TT * BB * HH];     // 128 MB: layer-1 h, [T][B][H]
__device__ float g_hlast[BB * HH];               // final h of layer 2
__device__ __nv_bfloat16 g_hhi[2 * BB * HH];     // h hi, double buffer [2][B][H]
__device__ __nv_bfloat16 g_hlo[2 * BB * HH];     // h lo
__device__ unsigned g_cnt;
__device__ unsigned g_gen;

// ---------------- helpers ----------------------------------------------------
__device__ __forceinline__ ull dupf(float v) {
    ull p; asm("mov.b64 %0, {%1, %1};" : "=l"(p) : "f"(v)); return p;
}
__device__ __forceinline__ void unpackf(ull p, float& lo, float& hi) {
    asm("mov.b64 {%0, %1}, %2;" : "=f"(lo), "=f"(hi) : "l"(p));
}
__device__ __forceinline__ void ffma2(ull& d, ull a, ull b) {
    asm("fma.rn.f32x2 %0, %1, %2, %0;" : "+l"(d) : "l"(a), "l"(b));
}
__device__ __forceinline__ float sigf(float v) { return 1.0f / (1.0f + __expf(-v)); }

__device__ __forceinline__ uint32_t smem_u32(const void* p) {
    uint32_t a;
    asm("{ .reg .u64 t; cvta.to.shared.u64 t, %1; cvt.u32.u64 %0, t; }"
        : "=r"(a) : "l"(p));
    return a;
}

__device__ __forceinline__ void ldmA(uint32_t& a0, uint32_t& a1,
                                     uint32_t& a2, uint32_t& a3, uint32_t addr) {
    asm volatile("ldmatrix.sync.aligned.m8n8.x4.shared.b16 {%0,%1,%2,%3}, [%4];"
                 : "=r"(a0), "=r"(a1), "=r"(a2), "=r"(a3) : "r"(addr));
}
__device__ __forceinline__ void ldmB(uint32_t& b0, uint32_t& b1, uint32_t addr) {
    asm volatile("ldmatrix.sync.aligned.m8n8.x2.trans.shared.b16 {%0,%1}, [%2];"
                 : "=r"(b0), "=r"(b1) : "r"(addr));
}
__device__ __forceinline__ void mma_bf16(float* d, uint32_t a0, uint32_t a1,
                                         uint32_t a2, uint32_t a3,
                                         uint32_t b0, uint32_t b1) {
    asm volatile(
        "mma.sync.aligned.m16n8k16.row.col.f32.bf16.bf16.f32 "
        "{%0,%1,%2,%3}, {%4,%5,%6,%7}, {%8,%9}, {%0,%1,%2,%3};"
        : "+f"(d[0]), "+f"(d[1]), "+f"(d[2]), "+f"(d[3])
        : "r"(a0), "r"(a1), "r"(a2), "r"(a3), "r"(b0), "r"(b1));
}

// ---------------------------------------------------------------------------
// Grid barrier (NB CTAs), cumulative, release/acquire
// ---------------------------------------------------------------------------
__device__ __forceinline__ void bar_arrive(unsigned target) {
    __syncthreads();
    if (threadIdx.x == 0) {
        unsigned old;
        asm volatile("atom.add.release.gpu.u32 %0, [%1], 1;"
                     : "=r"(old) : "l"(&g_cnt) : "memory");
        if (old == NB * target - 1) {
            asm volatile("st.release.gpu.u32 [%0], %1;"
                         :: "l"(&g_gen), "r"(target) : "memory");
        }
    }
}
__device__ __forceinline__ void bar_wait(unsigned target) {
    if (threadIdx.x == 0) {
        unsigned g;
        do {
            asm volatile("ld.acquire.gpu.u32 %0, [%1];"
                         : "=r"(g) : "l"(&g_gen) : "memory");
        } while (g < target);
    }
    __syncthreads();
}

// ---------------------------------------------------------------------------
// Init: zero h0 (bf16 hi/lo phase 0) + reset barrier
// ---------------------------------------------------------------------------
__global__ void init_state_kernel() {
    int i = blockIdx.x * blockDim.x + threadIdx.x;
    if (i < BB * HH) {
        g_hhi[i] = __float2bfloat16(0.f);
        g_hlo[i] = __float2bfloat16(0.f);
    }
    if (i == 0) { g_cnt = 0; g_gen = 0; }
}

// ---------------------------------------------------------------------------
// fp32 GEMM (unchanged from the 13.4ms round):
// Cout[m][n] = sum_k A(m,k)*Bm[k][n] + bias[n], m = t*B+b, [T][B][4H] out.
//   xmap=1: A(m,k) = x[b][t][k];  xmap=0: A rows contiguous (A + m*F)
// ---------------------------------------------------------------------------
__global__ void __launch_bounds__(256, 2)
gemm_xw_kernel(const float* __restrict__ A,
               const float* __restrict__ Bm,
               const float* __restrict__ bias,
               float* __restrict__ Cout,
               int xmap)
{
    __shared__ ull AsD[16 * ASTRIDE];
    __shared__ float Bs[16][128];

    const int tid = threadIdx.x;
    const int tx = tid & 15;
    const int ty = tid >> 4;
    const int n0 = blockIdx.x * 128;
    const int m0 = blockIdx.y * 128;

    float b8[8];
    *(float4*)&b8[0] = *(const float4*)(bias + n0 + tx * 8);
    *(float4*)&b8[4] = *(const float4*)(bias + n0 + tx * 8 + 4);

    const int lrow = tid >> 1;
    const int lkh  = tid & 1;
    const int m = m0 + lrow;
    long long arow;
    if (xmap) arow = ((long long)(m & (BB - 1)) * TT + (m >> 8)) * FF;
    else      arow = (long long)m * FF;

    ull acc[8][4];
#pragma unroll
    for (int r = 0; r < 8; r++)
#pragma unroll
        for (int c = 0; c < 4; c++) acc[r][c] = 0ULL;

    for (int k0 = 0; k0 < FF; k0 += 16) {
        float4 a0 = *(const float4*)(A + arow + k0 + lkh * 8);
        float4 a1 = *(const float4*)(A + arow + k0 + lkh * 8 + 4);
        const int kb = lkh * 8;
        AsD[(kb + 0) * ASTRIDE + lrow] = dupf(a0.x);
        AsD[(kb + 1) * ASTRIDE + lrow] = dupf(a0.y);
        AsD[(kb + 2) * ASTRIDE + lrow] = dupf(a0.z);
        AsD[(kb + 3) * ASTRIDE + lrow] = dupf(a0.w);
        AsD[(kb + 4) * ASTRIDE + lrow] = dupf(a1.x);
        AsD[(kb + 5) * ASTRIDE + lrow] = dupf(a1.y);
        AsD[(kb + 6) * ASTRIDE + lrow] = dupf(a1.z);
        AsD[(kb + 7) * ASTRIDE + lrow] = dupf(a1.w);
#pragma unroll
        for (int i = 0; i < 2; i++) {
            const int idx = (tid + i * 256) * 4;
            const int kk = idx >> 7;
            const int cc = idx & 127;
            *(float4*)&Bs[kk][cc] =
                *(const float4*)(Bm + (size_t)(k0 + kk) * GG + n0 + cc);
        }
        __syncthreads();
#pragma unroll
        for (int kk = 0; kk < 16; kk++) {
            const ull* ar = &AsD[kk * ASTRIDE + ty * 8];
            ull2 a01 = *(const ull2*)(ar + 0);
            ull2 a23 = *(const ull2*)(ar + 2);
            ull2 a45 = *(const ull2*)(ar + 4);
            ull2 a67 = *(const ull2*)(ar + 6);
            ull2 b01 = *(const ull2*)&Bs[kk][tx * 8];
            ull2 b23 = *(const ull2*)&Bs[kk][tx * 8 + 4];
            ffma2(acc[0][0], a01.x, b01.x); ffma2(acc[0][1], a01.x, b01.y);
            ffma2(acc[0][2], a01.x, b23.x); ffma2(acc[0][3], a01.x, b23.y);
            ffma2(acc[1][0], a01.y, b01.x); ffma2(acc[1][1], a01.y, b01.y);
            ffma2(acc[1][2], a01.y, b23.x); ffma2(acc[1][3], a01.y, b23.y);
            ffma2(acc[2][0], a23.x, b01.x); ffma2(acc[2][1], a23.x, b01.y);
            ffma2(acc[2][2], a23.x, b23.x); ffma2(acc[2][3], a23.x, b23.y);
            ffma2(acc[3][0], a23.y, b01.x); ffma2(acc[3][1], a23.y, b01.y);
            ffma2(acc[3][2], a23.y, b23.x); ffma2(acc[3][3], a23.y, b23.y);
            ffma2(acc[4][0], a45.x, b01.x); ffma2(acc[4][1], a45.x, b01.y);
            ffma2(acc[4][2], a45.x, b23.x); ffma2(acc[4][3], a45.x, b23.y);
            ffma2(acc[5][0], a45.y, b01.x); ffma2(acc[5][1], a45.y, b01.y);
            ffma2(acc[5][2], a45.y, b23.x); ffma2(acc[5][3], a45.y, b23.y);
            ffma2(acc[6][0], a67.x, b01.x); ffma2(acc[6][1], a67.x, b01.y);
            ffma2(acc[6][2], a67.x, b23.x); ffma2(acc[6][3], a67.x, b23.y);
            ffma2(acc[7][0], a67.y, b01.x); ffma2(acc[7][1], a67.y, b01.y);
            ffma2(acc[7][2], a67.y, b23.x); ffma2(acc[7][3], a67.y, b23.y);
        }
        __syncthreads();
    }

    float o[8][8];
#pragma unroll
    for (int r = 0; r < 8; r++) {
#pragma unroll
        for (int c = 0; c < 4; c++) unpackf(acc[r][c], o[r][2 * c], o[r][2 * c + 1]);
#pragma unroll
        for (int j = 0; j < 8; j++) o[r][j] += b8[j];
    }
    float* cb = Cout + (size_t)(m0 + ty * 8) * GG + n0 + tx * 8;
#pragma unroll
    for (int r = 0; r < 8; r++) {
        *(float4*)(cb + (size_t)r * GG)     = *(float4*)&o[r][0];
        *(float4*)(cb + (size_t)r * GG + 4) = *(float4*)&o[r][4];
    }
}

// ---------------------------------------------------------------------------
// Persistent MMA LSTM layer. 128 CTAs x 256 thr (8 warps).
// CTA tile: 64 batch rows (m0) x [8 hc (hc0) x 4 gates].
// Warp w: m-subtile (w&3)*16, gate pair (w>>2)*2 + {0,1}.
// z = Ahi*Bhi + Ahi*Blo + Alo*Bhi via mma.sync bf16 (3 independent acc sets).
// U resident in smem bf16 hi/lo [gate][k][8n]; h via global bf16 hi/lo dbuf.
// c in fp32 regs (2/thread) for all 512 steps; xW fp32 added in epilogue.
// ---------------------------------------------------------------------------
#define SA_STRIDE 528                 /* bytes per A row: 256 bf16 + 8 pad     */
#define S_AHI 0
#define S_ALO (S_AHI + 64 * SA_STRIDE)            /* 33792 */
#define S_BHI (S_ALO + 64 * SA_STRIDE)            /* 67584 */
#define S_BLO (S_BHI + 4 * 256 * 16)              /* 83968 */
#define S_Z   (S_BLO + 4 * 256 * 16)              /* 100352 */
#define ZST   36                                  /* z row stride (floats)    */
#define S_TOT (S_Z + 64 * ZST * 4)                /* 109568 */

__global__ void __launch_bounds__(256, 1)
lstm_mma_kernel(const float* __restrict__ xw_all,   // [T][B][4H]
                const float* __restrict__ U,        // [H][4H]
                float* __restrict__ hseq,           // [T][B][H] or null
                float* __restrict__ hlast,          // [B][H]
                __nv_bfloat16* __restrict__ hhi,    // [2][B*H]
                __nv_bfloat16* __restrict__ hlo)    // [2][B*H]
{
    extern __shared__ char smem[];
    const uint32_t sb = smem_u32(smem);
    float* zs = (float*)(smem + S_Z);

    const int tid  = threadIdx.x;
    const int w    = tid >> 5;
    const int lane = tid & 31;
    const int m0   = (blockIdx.x >> 5) * 64;
    const int hc0  = (blockIdx.x & 31) * 8;

    // ---- one-time: U gate slices -> smem bf16 hi/lo, [gate][k][8 cols] ----
    // row k of gate g: 8 bf16 (16B), ldmatrix.trans-ready.
    for (int i = tid; i < 4 * 256; i += 256) {
        const int g = i >> 8;
        const int k = i & 255;
        const float* up = U + (size_t)k * GG + g * HH + hc0;
        __nv_bfloat16 hi8[8], lo8[8];
#pragma unroll
        for (int j = 0; j < 8; j++) {
            const float u = up[j];
            hi8[j] = __float2bfloat16_rn(u);
            lo8[j] = __float2bfloat16_rn(u - __bfloat162float(hi8[j]));
        }
        *(uint4*)(smem + S_BHI + i * 16) = *(uint4*)hi8;
        *(uint4*)(smem + S_BLO + i * 16) = *(uint4*)lo8;
    }

    float creg[2] = {0.f, 0.f};

    // epilogue ownership: row = m0 + tid/4, cols hc0 + (tid%4)*2 + {0,1}
    const int erow = m0 + (tid >> 2);
    const int ecol = (tid & 3) * 2;

    // prefetch xw(t=0): 4 gates x 2 cols
    float2 xwf[4];
#pragma unroll
    for (int g = 0; g < 4; g++)
        xwf[g] = *(const float2*)(xw_all + (size_t)erow * GG + g * HH + hc0 + ecol);

    // MMA addressing
    const int mbase = (w & 3) * 16;
    const int ga = (w >> 2) * 2;
    const uint32_t aAddrHi = sb + S_AHI + (mbase + (lane & 15)) * SA_STRIDE
                            + (lane >> 4) * 16;
    const uint32_t aAddrLo = aAddrHi + (S_ALO - S_AHI);
    const uint32_t bAddrHi0 = sb + S_BHI + (ga + 0) * 4096 + (lane & 15) * 16;
    const uint32_t bAddrHi1 = sb + S_BHI + (ga + 1) * 4096 + (lane & 15) * 16;
    const uint32_t bAddrLo0 = bAddrHi0 + (S_BLO - S_BHI);
    const uint32_t bAddrLo1 = bAddrHi1 + (S_BLO - S_BHI);

    // h staging: 8 uint4 chunks per matrix per thread
    const int srow = tid >> 2;            // via chunk id below
    (void)srow;

    for (int t = 0; t < TT; t++) {
        bar_wait((unsigned)t);
        const int ph = t & 1;
        const __nv_bfloat16* shi = hhi + (size_t)ph * BB * HH;
        const __nv_bfloat16* slo = hlo + (size_t)ph * BB * HH;

        // ---- stage h rows m0..m0+63 into A_hi / A_lo smem ----
#pragma unroll
        for (int i = 0; i < 8; i++) {
            const int id = tid + i * 256;       // 0..2047
            const int r  = id >> 5;             // 0..63
            const int cc = id & 31;             // 16B chunk
            const uint4 vh = *((const uint4*)(shi + (size_t)(m0 + r) * HH) + cc);
            const uint4 vl = *((const uint4*)(slo + (size_t)(m0 + r) * HH) + cc);
            *(uint4*)(smem + S_AHI + r * SA_STRIDE + cc * 16) = vh;
            *(uint4*)(smem + S_ALO + r * SA_STRIDE + cc * 16) = vl;
        }
        __syncthreads();

        // ---- MMA mainloop: 16 k-chunks, 3 split terms, 2 gates ----
        float d[2][3][4];
#pragma unroll
        for (int gt = 0; gt < 2; gt++)
#pragma unroll
            for (int s = 0; s < 3; s++)
#pragma unroll
                for (int q = 0; q < 4; q++) d[gt][s][q] = 0.f;

#pragma unroll
        for (int kc = 0; kc < 16; kc++) {
            uint32_t ah0, ah1, ah2, ah3, al0, al1, al2, al3;
            ldmA(ah0, ah1, ah2, ah3, aAddrHi + kc * 32);
            ldmA(al0, al1, al2, al3, aAddrLo + kc * 32);
            uint32_t bh00, bh01, bl00, bl01, bh10, bh11, bl10, bl11;
            ldmB(bh00, bh01, bAddrHi0 + kc * 256);
            ldmB(bl00, bl01, bAddrLo0 + kc * 256);
            ldmB(bh10, bh11, bAddrHi1 + kc * 256);
            ldmB(bl10, bl11, bAddrLo1 + kc * 256);
            mma_bf16(d[0][0], ah0, ah1, ah2, ah3, bh00, bh01);
            mma_bf16(d[0][1], ah0, ah1, ah2, ah3, bl00, bl01);
            mma_bf16(d[0][2], al0, al1, al2, al3, bh00, bh01);
            mma_bf16(d[1][0], ah0, ah1, ah2, ah3, bh10, bh11);
            mma_bf16(d[1][1], ah0, ah1, ah2, ah3, bl10, bl11);
            mma_bf16(d[1][2], al0, al1, al2, al3, bh10, bh11);
        }

        // ---- store z fragments to smem ----
#pragma unroll
        for (int gt = 0; gt < 2; gt++) {
            const int gcol = (ga + gt) * 8 + (lane & 3) * 2;
            const int r0 = mbase + (lane >> 2);
            float2 v0 = make_float2(d[gt][0][0] + d[gt][1][0] + d[gt][2][0],
                                    d[gt][0][1] + d[gt][1][1] + d[gt][2][1]);
            float2 v1 = make_float2(d[gt][0][2] + d[gt][1][2] + d[gt][2][2],
                                    d[gt][0][3] + d[gt][1][3] + d[gt][2][3]);
            *(float2*)&zs[r0 * ZST + gcol]       = v0;
            *(float2*)&zs[(r0 + 8) * ZST + gcol] = v1;
        }
        __syncthreads();

        // ---- epilogue: gates -> c,h ----
        const int zr = (tid >> 2) * ZST + ecol;
        float2 zi2 = *(float2*)&zs[zr + 0];
        float2 zf2 = *(float2*)&zs[zr + 8];
        float2 zg2 = *(float2*)&zs[zr + 16];
        float2 zo2 = *(float2*)&zs[zr + 24];

        float hv[2];
        {
            const float zi = zi2.x + xwf[0].x, zf = zf2.x + xwf[1].x;
            const float zg = zg2.x + xwf[2].x, zo = zo2.x + xwf[3].x;
            const float ig = sigf(zi), fg = sigf(zf);
            const float gg = __tanhf(zg), og = sigf(zo);
            const float cn = fg * creg[0] + ig * gg;
            creg[0] = cn;
            hv[0] = og * __tanhf(cn);
        }
        {
            const float zi = zi2.y + xwf[0].y, zf = zf2.y + xwf[1].y;
            const float zg = zg2.y + xwf[2].y, zo = zo2.y + xwf[3].y;
            const float ig = sigf(zi), fg = sigf(zf);
            const float gg = __tanhf(zg), og = sigf(zo);
            const float cn = fg * creg[1] + ig * gg;
            creg[1] = cn;
            hv[1] = og * __tanhf(cn);
        }

        // split h -> bf16 hi/lo, write next-phase buffers
        const __nv_bfloat16 h0h = __float2bfloat16_rn(hv[0]);
        const __nv_bfloat16 h1h = __float2bfloat16_rn(hv[1]);
        const __nv_bfloat16 h0l = __float2bfloat16_rn(hv[0] - __bfloat162float(h0h));
        const __nv_bfloat16 h1l = __float2bfloat16_rn(hv[1] - __bfloat162float(h1h));
        const uint32_t phi = (uint32_t)__bfloat16_as_ushort(h0h)
                           | ((uint32_t)__bfloat16_as_ushort(h1h) << 16);
        const uint32_t plo = (uint32_t)__bfloat16_as_ushort(h0l)
                           | ((uint32_t)__bfloat16_as_ushort(h1l) << 16);
        const int np = ph ^ 1;
        const size_t hoff = (size_t)np * BB * HH + (size_t)erow * HH + hc0 + ecol;
        *(uint32_t*)(hhi + hoff) = phi;
        *(uint32_t*)(hlo + hoff) = plo;

        if (hseq) {
            *(float2*)(hseq + ((size_t)t * BB + erow) * HH + hc0 + ecol)
                = make_float2(hv[0], hv[1]);
        } else if (t == TT - 1) {
            *(float2*)(hlast + (size_t)erow * HH + hc0 + ecol)
                = make_float2(hv[0], hv[1]);
        }

        bar_arrive((unsigned)(t + 1));

        // prefetch next xw while other CTAs catch up
        if (t + 1 < TT) {
            const float* xr = xw_all + ((size_t)(t + 1) * BB + erow) * GG;
#pragma unroll
            for (int g = 0; g < 4; g++)
                xwf[g] = *(const float2*)(xr + g * HH + hc0 + ecol);
        }
    }
}

// ---------------------------------------------------------------------------
// out[b] = sum_k hlast[b][k] * Wd[k] + bd[0]
// ---------------------------------------------------------------------------
__global__ void dense_out_kernel(const float* __restrict__ hlast,  // [B][H]
                                 const float* __restrict__ Wd,
                                 const float* __restrict__ bd,
                                 float* __restrict__ out)
{
    __shared__ float red[256];
    const int b = blockIdx.x;
    const int k = threadIdx.x;
    red[k] = hlast[b * HH + k] * Wd[k];
    __syncthreads();
    for (int s = 128; s > 0; s >>= 1) {
        if (k < s) red[k] += red[k + s];
        __syncthreads();
    }
    if (k == 0) out[b] = red[0] + bd[0];
}

// ---------------------------------------------------------------------------
// Launch: 7 graph nodes.
// ---------------------------------------------------------------------------
extern "C" void kernel_launch(void* const* d_in, const int* in_sizes, int n_in,
                              void* d_out, int out_size)
{
    const float* x  = (const float*)d_in[0];
    const float* W1 = (const float*)d_in[1];
    const float* U1 = (const float*)d_in[2];
    const float* b1 = (const float*)d_in[3];
    const float* W2 = (const float*)d_in[4];
    const float* U2 = (const float*)d_in[5];
    const float* b2 = (const float*)d_in[6];
    const float* Wd = (const float*)d_in[7];
    const float* bd = (const float*)d_in[8];
    float* out = (float*)d_out;

    float *xw, *h1, *hlast;
    __nv_bfloat16 *hhi, *hlo;
    cudaGetSymbolAddress((void**)&xw, g_xw);
    cudaGetSymbolAddress((void**)&h1, g_h1);
    cudaGetSymbolAddress((void**)&hlast, g_hlast);
    cudaGetSymbolAddress((void**)&hhi, g_hhi);
    cudaGetSymbolAddress((void**)&hlo, g_hlo);

    cudaFuncSetAttribute(lstm_mma_kernel,
                         cudaFuncAttributeMaxDynamicSharedMemorySize, S_TOT);

    const dim3 gemm_grid(GG / 128, (TT * BB) / 128);

    // Layer 1
    gemm_xw_kernel<<<gemm_grid, 256>>>(x, W1, b1, xw, 1);
    init_state_kernel<<<(BB * HH + 255) / 256, 256>>>();
    lstm_mma_kernel<<<NB, 256, S_TOT>>>(xw, U1, h1, hlast, hhi, hlo);

    // Layer 2
    gemm_xw_kernel<<<gemm_grid, 256>>>(h1, W2, b2, xw, 0);
    init_state_kernel<<<(BB * HH + 255) / 256, 256>>>();
    lstm_mma_kernel<<<NB, 256, S_TOT>>>(xw, U2, (float*)0, hlast, hhi, hlo);

    dense_out_kernel<<<BB, 256>>>(hlast, Wd, bd, out);
}

// round 7
// speedup vs baseline: 2.8066x; 1.2892x over previous
#include <cuda_runtime.h>
#include <cuda_bf16.h>
#include <math.h>
#include <stdint.h>

#define BB 256
#define TT 512
#define FF 256
#define HH 256
#define GG 1024     /* 4*H */
#define NB 128      /* persistent CTAs */
#define MM (TT * BB)

typedef unsigned long long ull;

// ---------------- device globals (no runtime allocation) --------------------
__device__ float g_xw[(size_t)TT * BB * GG];        // 512 MB: xW(+b), [T][B][4H]
__device__ __nv_bfloat16 g_xhi[(size_t)MM * FF];    // 64 MB: x hi, row m=t*B+b
__device__ __nv_bfloat16 g_xlo[(size_t)MM * FF];    // 64 MB
__device__ __nv_bfloat16 g_h1hi[(size_t)MM * HH];   // 64 MB: layer-1 h hi
__device__ __nv_bfloat16 g_h1lo[(size_t)MM * HH];   // 64 MB
__device__ __nv_bfloat16 g_whi[FF * GG];            // 512 KB: W hi (per layer)
__device__ __nv_bfloat16 g_wlo[FF * GG];
__device__ float g_hlast[BB * HH];                  // final h of layer 2
__device__ __nv_bfloat16 g_hhi[2 * BB * HH];        // h dbuf hi [2][B][H]
__device__ __nv_bfloat16 g_hlo[2 * BB * HH];        // h dbuf lo
__device__ unsigned g_cnt;
__device__ unsigned g_gen;

// ---------------- helpers ----------------------------------------------------
__device__ __forceinline__ float sigf(float v) { return 1.0f / (1.0f + __expf(-v)); }

__device__ __forceinline__ uint32_t smem_u32(const void* p) {
    uint32_t a;
    asm("{ .reg .u64 t; cvta.to.shared.u64 t, %1; cvt.u32.u64 %0, t; }"
        : "=r"(a) : "l"(p));
    return a;
}
__device__ __forceinline__ void ldmA(uint32_t& a0, uint32_t& a1,
                                     uint32_t& a2, uint32_t& a3, uint32_t addr) {
    asm volatile("ldmatrix.sync.aligned.m8n8.x4.shared.b16 {%0,%1,%2,%3}, [%4];"
                 : "=r"(a0), "=r"(a1), "=r"(a2), "=r"(a3) : "r"(addr));
}
__device__ __forceinline__ void ldmB(uint32_t& b0, uint32_t& b1, uint32_t addr) {
    asm volatile("ldmatrix.sync.aligned.m8n8.x2.trans.shared.b16 {%0,%1}, [%2];"
                 : "=r"(b0), "=r"(b1) : "r"(addr));
}
__device__ __forceinline__ void mma_bf16(float* d, uint32_t a0, uint32_t a1,
                                         uint32_t a2, uint32_t a3,
                                         uint32_t b0, uint32_t b1) {
    asm volatile(
        "mma.sync.aligned.m16n8k16.row.col.f32.bf16.bf16.f32 "
        "{%0,%1,%2,%3}, {%4,%5,%6,%7}, {%8,%9}, {%0,%1,%2,%3};"
        : "+f"(d[0]), "+f"(d[1]), "+f"(d[2]), "+f"(d[3])
        : "r"(a0), "r"(a1), "r"(a2), "r"(a3), "r"(b0), "r"(b1));
}
__device__ __forceinline__ void split_bf16(float v, __nv_bfloat16& hi, __nv_bfloat16& lo) {
    hi = __float2bfloat16_rn(v);
    lo = __float2bfloat16_rn(v - __bfloat162float(hi));
}

// ---------------------------------------------------------------------------
// Grid barrier (NB CTAs), cumulative, release/acquire
// ---------------------------------------------------------------------------
__device__ __forceinline__ void bar_arrive(unsigned target) {
    __syncthreads();
    if (threadIdx.x == 0) {
        unsigned old;
        asm volatile("atom.add.release.gpu.u32 %0, [%1], 1;"
                     : "=r"(old) : "l"(&g_cnt) : "memory");
        if (old == NB * target - 1) {
            asm volatile("st.release.gpu.u32 [%0], %1;"
                         :: "l"(&g_gen), "r"(target) : "memory");
        }
    }
}
__device__ __forceinline__ void bar_wait(unsigned target) {
    if (threadIdx.x == 0) {
        unsigned g;
        do {
            asm volatile("ld.acquire.gpu.u32 %0, [%1];"
                         : "=r"(g) : "l"(&g_gen) : "memory");
        } while (g < target);
    }
    __syncthreads();
}

// ---------------------------------------------------------------------------
// Init: zero h0 (bf16 hi/lo phase 0) + reset barrier
// ---------------------------------------------------------------------------
__global__ void init_state_kernel() {
    int i = blockIdx.x * blockDim.x + threadIdx.x;
    if (i < BB * HH) {
        g_hhi[i] = __float2bfloat16(0.f);
        g_hlo[i] = __float2bfloat16(0.f);
    }
    if (i == 0) { g_cnt = 0; g_gen = 0; }
}

// ---------------------------------------------------------------------------
// conv_x: x[B][T][F] fp32 -> xhi/xlo bf16 rows m = t*B+b. 32 thr/row, 8 el/thr.
// ---------------------------------------------------------------------------
__global__ void conv_x_kernel(const float* __restrict__ x,
                              __nv_bfloat16* __restrict__ xhi,
                              __nv_bfloat16* __restrict__ xlo)
{
    const int gid = blockIdx.x * 256 + threadIdx.x;
    const int m = gid >> 5;
    const int c = (gid & 31) * 8;
    const int b = m & (BB - 1);
    const int t = m >> 8;
    const float* src = x + ((size_t)b * TT + t) * FF + c;
    float4 v0 = *(const float4*)src;
    float4 v1 = *(const float4*)(src + 4);
    float vv[8] = {v0.x, v0.y, v0.z, v0.w, v1.x, v1.y, v1.z, v1.w};
    __nv_bfloat16 hi8[8], lo8[8];
#pragma unroll
    for (int j = 0; j < 8; j++) split_bf16(vv[j], hi8[j], lo8[j]);
    *(uint4*)(xhi + (size_t)m * FF + c) = *(uint4*)hi8;
    *(uint4*)(xlo + (size_t)m * FF + c) = *(uint4*)lo8;
}

// ---------------------------------------------------------------------------
// conv_w: W[F][4H] fp32 -> whi/wlo bf16. 4 el/thr.
// ---------------------------------------------------------------------------
__global__ void conv_w_kernel(const float* __restrict__ W,
                              __nv_bfloat16* __restrict__ whi,
                              __nv_bfloat16* __restrict__ wlo)
{
    const int i = (blockIdx.x * 256 + threadIdx.x) * 4;
    float4 v = *(const float4*)(W + i);
    float vv[4] = {v.x, v.y, v.z, v.w};
    __nv_bfloat16 hi4[4], lo4[4];
#pragma unroll
    for (int j = 0; j < 4; j++) split_bf16(vv[j], hi4[j], lo4[j]);
    *(uint2*)(whi + i) = *(uint2*)hi4;
    *(uint2*)(wlo + i) = *(uint2*)lo4;
}

// ---------------------------------------------------------------------------
// bf16-split MMA GEMM: Cout[m][n] = sum_k A[m][k]*B[k][n] + bias[n]
// A, B given as bf16 hi/lo; z = Ahi*Bhi + Ahi*Blo + Alo*Bhi (fp32 accum).
// CTA tile 128m x 64n, BK=32, 256 thr (8 warps: 4m x 2n), reg-prefetch dbuf.
// ---------------------------------------------------------------------------
#define GA_STR 80   /* bytes per A smem row: 32 bf16 + 8 pad */
#define GB_STR 144  /* bytes per B smem row: 64 bf16 + 8 pad */
#define GS_AHI 0
#define GS_ALO (GS_AHI + 128 * GA_STR)
#define GS_BHI (GS_ALO + 128 * GA_STR)
#define GS_BLO (GS_BHI + 32 * GB_STR)
#define GS_TOT (GS_BLO + 32 * GB_STR)

__global__ void __launch_bounds__(256, 2)
gemm_bf16_kernel(const __nv_bfloat16* __restrict__ Ahi_g,
                 const __nv_bfloat16* __restrict__ Alo_g,
                 const __nv_bfloat16* __restrict__ Bhi_g,
                 const __nv_bfloat16* __restrict__ Blo_g,
                 const float* __restrict__ bias,
                 float* __restrict__ Cout)
{
    __shared__ char gsm[GS_TOT];
    const uint32_t sb = smem_u32(gsm);

    const int tid  = threadIdx.x;
    const int w    = tid >> 5;
    const int lane = tid & 31;
    const int n0 = blockIdx.x * 64;
    const int m0 = blockIdx.y * 128;
    const int wm = (w >> 1) * 32;
    const int wn = (w & 1) * 32;

    // staging indices
    const int ar = tid >> 1;                 // A row 0..127
    const int ac = (tid & 1) * 2;            // 2 chunks of 16B
    const size_t aoff = (size_t)(m0 + ar) * FF;
    const int br = tid >> 3;                 // B row 0..31
    const int bc = tid & 7;                  // 16B chunk

    // prefetch k-block 0
    uint4 pAh0 = *(const uint4*)(Ahi_g + aoff + (ac + 0) * 8);
    uint4 pAh1 = *(const uint4*)(Ahi_g + aoff + (ac + 1) * 8);
    uint4 pAl0 = *(const uint4*)(Alo_g + aoff + (ac + 0) * 8);
    uint4 pAl1 = *(const uint4*)(Alo_g + aoff + (ac + 1) * 8);
    uint4 pBh  = *(const uint4*)(Bhi_g + (size_t)br * GG + n0 + bc * 8);
    uint4 pBl  = *(const uint4*)(Blo_g + (size_t)br * GG + n0 + bc * 8);

    float acc[2][4][4];
#pragma unroll
    for (int mt = 0; mt < 2; mt++)
#pragma unroll
        for (int nt = 0; nt < 4; nt++)
#pragma unroll
            for (int q = 0; q < 4; q++) acc[mt][nt][q] = 0.f;

    const uint32_t aAddr = sb + GS_AHI + (wm + (lane & 15)) * GA_STR + (lane >> 4) * 16;
    const uint32_t bAddr = sb + GS_BHI + (lane & 15) * GB_STR + wn * 2;

    for (int kb = 0; kb < 8; kb++) {
        // store staged regs
        *(uint4*)(gsm + GS_AHI + ar * GA_STR + (ac + 0) * 16) = pAh0;
        *(uint4*)(gsm + GS_AHI + ar * GA_STR + (ac + 1) * 16) = pAh1;
        *(uint4*)(gsm + GS_ALO + ar * GA_STR + (ac + 0) * 16) = pAl0;
        *(uint4*)(gsm + GS_ALO + ar * GA_STR + (ac + 1) * 16) = pAl1;
        *(uint4*)(gsm + GS_BHI + br * GB_STR + bc * 16) = pBh;
        *(uint4*)(gsm + GS_BLO + br * GB_STR + bc * 16) = pBl;
        // issue next loads (overlap with compute)
        if (kb < 7) {
            const int k1 = (kb + 1) * 32;
            pAh0 = *(const uint4*)(Ahi_g + aoff + k1 + (ac + 0) * 8);
            pAh1 = *(const uint4*)(Ahi_g + aoff + k1 + (ac + 1) * 8);
            pAl0 = *(const uint4*)(Alo_g + aoff + k1 + (ac + 0) * 8);
            pAl1 = *(const uint4*)(Alo_g + aoff + k1 + (ac + 1) * 8);
            pBh  = *(const uint4*)(Bhi_g + (size_t)(k1 + br) * GG + n0 + bc * 8);
            pBl  = *(const uint4*)(Blo_g + (size_t)(k1 + br) * GG + n0 + bc * 8);
        }
        __syncthreads();

#pragma unroll
        for (int kc = 0; kc < 2; kc++) {
            uint32_t ah[2][4], al[2][4];
#pragma unroll
            for (int mt = 0; mt < 2; mt++) {
                const uint32_t a = aAddr + mt * 16 * GA_STR + kc * 32;
                ldmA(ah[mt][0], ah[mt][1], ah[mt][2], ah[mt][3], a);
                ldmA(al[mt][0], al[mt][1], al[mt][2], al[mt][3],
                     a + (GS_ALO - GS_AHI));
            }
            uint32_t bh[4][2], bl[4][2];
#pragma unroll
            for (int nt = 0; nt < 4; nt++) {
                const uint32_t b = bAddr + kc * 16 * GB_STR + nt * 16;
                ldmB(bh[nt][0], bh[nt][1], b);
                ldmB(bl[nt][0], bl[nt][1], b + (GS_BLO - GS_BHI));
            }
#pragma unroll
            for (int mt = 0; mt < 2; mt++)
#pragma unroll
                for (int nt = 0; nt < 4; nt++) {
                    mma_bf16(acc[mt][nt], ah[mt][0], ah[mt][1], ah[mt][2], ah[mt][3],
                             bh[nt][0], bh[nt][1]);
                    mma_bf16(acc[mt][nt], ah[mt][0], ah[mt][1], ah[mt][2], ah[mt][3],
                             bl[nt][0], bl[nt][1]);
                    mma_bf16(acc[mt][nt], al[mt][0], al[mt][1], al[mt][2], al[mt][3],
                             bh[nt][0], bh[nt][1]);
                }
        }
        __syncthreads();
    }

    // epilogue: + bias, fp32 out
#pragma unroll
    for (int mt = 0; mt < 2; mt++) {
        const int mrow = m0 + wm + mt * 16 + (lane >> 2);
#pragma unroll
        for (int nt = 0; nt < 4; nt++) {
            const int n = n0 + wn + nt * 8 + (lane & 3) * 2;
            const float2 b2 = *(const float2*)(bias + n);
            float* o0 = Cout + (size_t)mrow * GG + n;
            float* o1 = Cout + (size_t)(mrow + 8) * GG + n;
            *(float2*)o0 = make_float2(acc[mt][nt][0] + b2.x, acc[mt][nt][1] + b2.y);
            *(float2*)o1 = make_float2(acc[mt][nt][2] + b2.x, acc[mt][nt][3] + b2.y);
        }
    }
}

// ---------------------------------------------------------------------------
// Persistent MMA LSTM layer (as R6, but hseq emitted as bf16 hi/lo).
// 128 CTAs x 256 thr. CTA: 64 rows x [8 hc x 4 gates]. Warp: 16m x 2 gates.
// ---------------------------------------------------------------------------
#define SA_STRIDE 528
#define S_AHI 0
#define S_ALO (S_AHI + 64 * SA_STRIDE)
#define S_BHI (S_ALO + 64 * SA_STRIDE)
#define S_BLO (S_BHI + 4 * 256 * 16)
#define S_Z   (S_BLO + 4 * 256 * 16)
#define ZST   36
#define S_TOT (S_Z + 64 * ZST * 4)

__global__ void __launch_bounds__(256, 1)
lstm_mma_kernel(const float* __restrict__ xw_all,       // [T][B][4H]
                const float* __restrict__ U,            // [H][4H]
                __nv_bfloat16* __restrict__ seqhi,      // [T*B][H] or null
                __nv_bfloat16* __restrict__ seqlo,      // [T*B][H] or null
                float* __restrict__ hlast,              // [B][H]
                __nv_bfloat16* __restrict__ hhi,        // [2][B*H]
                __nv_bfloat16* __restrict__ hlo)        // [2][B*H]
{
    extern __shared__ char smem[];
    const uint32_t sb = smem_u32(smem);
    float* zs = (float*)(smem + S_Z);

    const int tid  = threadIdx.x;
    const int w    = tid >> 5;
    const int lane = tid & 31;
    const int m0   = (blockIdx.x >> 5) * 64;
    const int hc0  = (blockIdx.x & 31) * 8;

    // one-time: U gate slices -> smem bf16 hi/lo [gate][k][8cols]
    for (int i = tid; i < 4 * 256; i += 256) {
        const int g = i >> 8;
        const int k = i & 255;
        const float* up = U + (size_t)k * GG + g * HH + hc0;
        __nv_bfloat16 hi8[8], lo8[8];
#pragma unroll
        for (int j = 0; j < 8; j++) split_bf16(up[j], hi8[j], lo8[j]);
        *(uint4*)(smem + S_BHI + i * 16) = *(uint4*)hi8;
        *(uint4*)(smem + S_BLO + i * 16) = *(uint4*)lo8;
    }

    float creg[2] = {0.f, 0.f};

    const int erow = m0 + (tid >> 2);
    const int ecol = (tid & 3) * 2;

    float2 xwf[4];
#pragma unroll
    for (int g = 0; g < 4; g++)
        xwf[g] = *(const float2*)(xw_all + (size_t)erow * GG + g * HH + hc0 + ecol);

    const int mbase = (w & 3) * 16;
    const int ga = (w >> 2) * 2;
    const uint32_t aAddrHi = sb + S_AHI + (mbase + (lane & 15)) * SA_STRIDE
                            + (lane >> 4) * 16;
    const uint32_t aAddrLo = aAddrHi + (S_ALO - S_AHI);
    const uint32_t bAddrHi0 = sb + S_BHI + (ga + 0) * 4096 + (lane & 15) * 16;
    const uint32_t bAddrHi1 = sb + S_BHI + (ga + 1) * 4096 + (lane & 15) * 16;
    const uint32_t bAddrLo0 = bAddrHi0 + (S_BLO - S_BHI);
    const uint32_t bAddrLo1 = bAddrHi1 + (S_BLO - S_BHI);

    for (int t = 0; t < TT; t++) {
        bar_wait((unsigned)t);
        const int ph = t & 1;
        const __nv_bfloat16* shi = hhi + (size_t)ph * BB * HH;
        const __nv_bfloat16* slo = hlo + (size_t)ph * BB * HH;

#pragma unroll
        for (int i = 0; i < 8; i++) {
            const int id = tid + i * 256;
            const int r  = id >> 5;
            const int cc = id & 31;
            const uint4 vh = *((const uint4*)(shi + (size_t)(m0 + r) * HH) + cc);
            const uint4 vl = *((const uint4*)(slo + (size_t)(m0 + r) * HH) + cc);
            *(uint4*)(smem + S_AHI + r * SA_STRIDE + cc * 16) = vh;
            *(uint4*)(smem + S_ALO + r * SA_STRIDE + cc * 16) = vl;
        }
        __syncthreads();

        float d[2][3][4];
#pragma unroll
        for (int gt = 0; gt < 2; gt++)
#pragma unroll
            for (int s = 0; s < 3; s++)
#pragma unroll
                for (int q = 0; q < 4; q++) d[gt][s][q] = 0.f;

#pragma unroll
        for (int kc = 0; kc < 16; kc++) {
            uint32_t ah0, ah1, ah2, ah3, al0, al1, al2, al3;
            ldmA(ah0, ah1, ah2, ah3, aAddrHi + kc * 32);
            ldmA(al0, al1, al2, al3, aAddrLo + kc * 32);
            uint32_t bh00, bh01, bl00, bl01, bh10, bh11, bl10, bl11;
            ldmB(bh00, bh01, bAddrHi0 + kc * 256);
            ldmB(bl00, bl01, bAddrLo0 + kc * 256);
            ldmB(bh10, bh11, bAddrHi1 + kc * 256);
            ldmB(bl10, bl11, bAddrLo1 + kc * 256);
            float* d00 = d[0][0]; float* d01 = d[0][1]; float* d02 = d[0][2];
            float* d10 = d[1][0]; float* d11 = d[1][1]; float* d12 = d[1][2];
            mma_bf16(d00, ah0, ah1, ah2, ah3, bh00, bh01);
            mma_bf16(d01, ah0, ah1, ah2, ah3, bl00, bl01);
            mma_bf16(d02, al0, al1, al2, al3, bh00, bh01);
            mma_bf16(d10, ah0, ah1, ah2, ah3, bh10, bh11);
            mma_bf16(d11, ah0, ah1, ah2, ah3, bl10, bl11);
            mma_bf16(d12, al0, al1, al2, al3, bh10, bh11);
        }

#pragma unroll
        for (int gt = 0; gt < 2; gt++) {
            const int gcol = (ga + gt) * 8 + (lane & 3) * 2;
            const int r0 = mbase + (lane >> 2);
            float2 v0 = make_float2(d[gt][0][0] + d[gt][1][0] + d[gt][2][0],
                                    d[gt][0][1] + d[gt][1][1] + d[gt][2][1]);
            float2 v1 = make_float2(d[gt][0][2] + d[gt][1][2] + d[gt][2][2],
                                    d[gt][0][3] + d[gt][1][3] + d[gt][2][3]);
            *(float2*)&zs[r0 * ZST + gcol]       = v0;
            *(float2*)&zs[(r0 + 8) * ZST + gcol] = v1;
        }
        __syncthreads();

        const int zr = (tid >> 2) * ZST + ecol;
        float2 zi2 = *(float2*)&zs[zr + 0];
        float2 zf2 = *(float2*)&zs[zr + 8];
        float2 zg2 = *(float2*)&zs[zr + 16];
        float2 zo2 = *(float2*)&zs[zr + 24];

        float hv[2];
        {
            const float zi = zi2.x + xwf[0].x, zf = zf2.x + xwf[1].x;
            const float zg = zg2.x + xwf[2].x, zo = zo2.x + xwf[3].x;
            const float ig = sigf(zi), fg = sigf(zf);
            const float gg = __tanhf(zg), og = sigf(zo);
            const float cn = fg * creg[0] + ig * gg;
            creg[0] = cn;
            hv[0] = og * __tanhf(cn);
        }
        {
            const float zi = zi2.y + xwf[0].y, zf = zf2.y + xwf[1].y;
            const float zg = zg2.y + xwf[2].y, zo = zo2.y + xwf[3].y;
            const float ig = sigf(zi), fg = sigf(zf);
            const float gg = __tanhf(zg), og = sigf(zo);
            const float cn = fg * creg[1] + ig * gg;
            creg[1] = cn;
            hv[1] = og * __tanhf(cn);
        }

        __nv_bfloat16 h0h, h1h, h0l, h1l;
        split_bf16(hv[0], h0h, h0l);
        split_bf16(hv[1], h1h, h1l);
        const uint32_t phi = (uint32_t)__bfloat16_as_ushort(h0h)
                           | ((uint32_t)__bfloat16_as_ushort(h1h) << 16);
        const uint32_t plo = (uint32_t)__bfloat16_as_ushort(h0l)
                           | ((uint32_t)__bfloat16_as_ushort(h1l) << 16);
        const int np = ph ^ 1;
        const size_t hoff = (size_t)np * BB * HH + (size_t)erow * HH + hc0 + ecol;
        *(uint32_t*)(hhi + hoff) = phi;
        *(uint32_t*)(hlo + hoff) = plo;

        if (seqhi) {
            const size_t soff = ((size_t)t * BB + erow) * HH + hc0 + ecol;
            *(uint32_t*)(seqhi + soff) = phi;
            *(uint32_t*)(seqlo + soff) = plo;
        } else if (t == TT - 1) {
            *(float2*)(hlast + (size_t)erow * HH + hc0 + ecol)
                = make_float2(hv[0], hv[1]);
        }

        bar_arrive((unsigned)(t + 1));

        if (t + 1 < TT) {
            const float* xr = xw_all + ((size_t)(t + 1) * BB + erow) * GG;
#pragma unroll
            for (int g = 0; g < 4; g++)
                xwf[g] = *(const float2*)(xr + g * HH + hc0 + ecol);
        }
    }
}

// ---------------------------------------------------------------------------
// out[b] = sum_k hlast[b][k] * Wd[k] + bd[0]
// ---------------------------------------------------------------------------
__global__ void dense_out_kernel(const float* __restrict__ hlast,
                                 const float* __restrict__ Wd,
                                 const float* __restrict__ bd,
                                 float* __restrict__ out)
{
    __shared__ float red[256];
    const int b = blockIdx.x;
    const int k = threadIdx.x;
    red[k] = hlast[b * HH + k] * Wd[k];
    __syncthreads();
    for (int s = 128; s > 0; s >>= 1) {
        if (k < s) red[k] += red[k + s];
        __syncthreads();
    }
    if (k == 0) out[b] = red[0] + bd[0];
}

// ---------------------------------------------------------------------------
// Launch
// ---------------------------------------------------------------------------
extern "C" void kernel_launch(void* const* d_in, const int* in_sizes, int n_in,
                              void* d_out, int out_size)
{
    const float* x  = (const float*)d_in[0];
    const float* W1 = (const float*)d_in[1];
    const float* U1 = (const float*)d_in[2];
    const float* b1 = (const float*)d_in[3];
    const float* W2 = (const float*)d_in[4];
    const float* U2 = (const float*)d_in[5];
    const float* b2 = (const float*)d_in[6];
    const float* Wd = (const float*)d_in[7];
    const float* bd = (const float*)d_in[8];
    float* out = (float*)d_out;

    float *xw, *hlast;
    __nv_bfloat16 *xhi, *xlo, *h1hi, *h1lo, *whi, *wlo, *hhi, *hlo;
    cudaGetSymbolAddress((void**)&xw, g_xw);
    cudaGetSymbolAddress((void**)&xhi, g_xhi);
    cudaGetSymbolAddress((void**)&xlo, g_xlo);
    cudaGetSymbolAddress((void**)&h1hi, g_h1hi);
    cudaGetSymbolAddress((void**)&h1lo, g_h1lo);
    cudaGetSymbolAddress((void**)&whi, g_whi);
    cudaGetSymbolAddress((void**)&wlo, g_wlo);
    cudaGetSymbolAddress((void**)&hlast, g_hlast);
    cudaGetSymbolAddress((void**)&hhi, g_hhi);
    cudaGetSymbolAddress((void**)&hlo, g_hlo);

    cudaFuncSetAttribute(lstm_mma_kernel,
                         cudaFuncAttributeMaxDynamicSharedMemorySize, S_TOT);

    const dim3 gemm_grid(GG / 64, MM / 128);

    // Layer 1
    conv_x_kernel<<<MM * 32 / 256, 256>>>(x, xhi, xlo);
    conv_w_kernel<<<FF * GG / 4 / 256, 256>>>(W1, whi, wlo);
    gemm_bf16_kernel<<<gemm_grid, 256>>>(xhi, xlo, whi, wlo, b1, xw);
    init_state_kernel<<<(BB * HH + 255) / 256, 256>>>();
    lstm_mma_kernel<<<NB, 256, S_TOT>>>(xw, U1, h1hi, h1lo, hlast, hhi, hlo);

    // Layer 2
    conv_w_kernel<<<FF * GG / 4 / 256, 256>>>(W2, whi, wlo);
    gemm_bf16_kernel<<<gemm_grid, 256>>>(h1hi, h1lo, whi, wlo, b2, xw);
    init_state_kernel<<<(BB * HH + 255) / 256, 256>>>();
    lstm_mma_kernel<<<NB, 256, S_TOT>>>(xw, U2, (__nv_bfloat16*)0,
                                        (__nv_bfloat16*)0, hlast, hhi, hlo);

    dense_out_kernel<<<BB, 256>>>(hlast, Wd, bd, out);
}

// round 8
// speedup vs baseline: 2.9467x; 1.0499x over previous
#include <cuda_runtime.h>
#include <cuda_bf16.h>
#include <math.h>
#include <stdint.h>

#define BB 256
#define TT 512
#define FF 256
#define HH 256
#define GG 1024     /* 4*H */
#define NB 128      /* persistent CTAs */
#define MM (TT * BB)

typedef unsigned long long ull;

// ---------------- device globals (no runtime allocation) --------------------
__device__ float g_xw[(size_t)TT * BB * GG];        // 512 MB: xW(+b), [T][B][4H]
__device__ __nv_bfloat16 g_xhi[(size_t)MM * FF];    // 64 MB
__device__ __nv_bfloat16 g_xlo[(size_t)MM * FF];    // 64 MB
__device__ __nv_bfloat16 g_h1hi[(size_t)MM * HH];   // 64 MB
__device__ __nv_bfloat16 g_h1lo[(size_t)MM * HH];   // 64 MB
__device__ __nv_bfloat16 g_whi[FF * GG];
__device__ __nv_bfloat16 g_wlo[FF * GG];
__device__ float g_hlast[BB * HH];
__device__ __nv_bfloat16 g_hhi[2 * BB * HH];        // h dbuf hi [2][B][H]
__device__ __nv_bfloat16 g_hlo[2 * BB * HH];        // h dbuf lo
__device__ unsigned g_flags[4 * 32];                 // per-group counters (128B apart)

// ---------------- helpers ----------------------------------------------------
__device__ __forceinline__ float sigf(float v) { return 1.0f / (1.0f + __expf(-v)); }

__device__ __forceinline__ uint32_t smem_u32(const void* p) {
    uint32_t a;
    asm("{ .reg .u64 t; cvta.to.shared.u64 t, %1; cvt.u32.u64 %0, t; }"
        : "=r"(a) : "l"(p));
    return a;
}
__device__ __forceinline__ void ldmA(uint32_t& a0, uint32_t& a1,
                                     uint32_t& a2, uint32_t& a3, uint32_t addr) {
    asm volatile("ldmatrix.sync.aligned.m8n8.x4.shared.b16 {%0,%1,%2,%3}, [%4];"
                 : "=r"(a0), "=r"(a1), "=r"(a2), "=r"(a3) : "r"(addr));
}
__device__ __forceinline__ void ldmB(uint32_t& b0, uint32_t& b1, uint32_t addr) {
    asm volatile("ldmatrix.sync.aligned.m8n8.x2.trans.shared.b16 {%0,%1}, [%2];"
                 : "=r"(b0), "=r"(b1) : "r"(addr));
}
__device__ __forceinline__ void mma_bf16(float* d, uint32_t a0, uint32_t a1,
                                         uint32_t a2, uint32_t a3,
                                         uint32_t b0, uint32_t b1) {
    asm volatile(
        "mma.sync.aligned.m16n8k16.row.col.f32.bf16.bf16.f32 "
        "{%0,%1,%2,%3}, {%4,%5,%6,%7}, {%8,%9}, {%0,%1,%2,%3};"
        : "+f"(d[0]), "+f"(d[1]), "+f"(d[2]), "+f"(d[3])
        : "r"(a0), "r"(a1), "r"(a2), "r"(a3), "r"(b0), "r"(b1));
}
__device__ __forceinline__ void split_bf16(float v, __nv_bfloat16& hi, __nv_bfloat16& lo) {
    hi = __float2bfloat16_rn(v);
    lo = __float2bfloat16_rn(v - __bfloat162float(hi));
}

// ---------------------------------------------------------------------------
// Group-scoped sync: 32 CTAs per batch-row group; counter IS the flag.
// ---------------------------------------------------------------------------
__device__ __forceinline__ void grp_arrive(int grp) {
    __syncthreads();
    if (threadIdx.x == 0) {
        unsigned old;
        asm volatile("atom.add.release.gpu.u32 %0, [%1], 1;"
                     : "=r"(old) : "l"(&g_flags[grp * 32]) : "memory");
    }
}
__device__ __forceinline__ void grp_wait(int grp, unsigned target) {
    if (threadIdx.x == 0) {
        unsigned g;
        do {
            asm volatile("ld.acquire.gpu.u32 %0, [%1];"
                         : "=r"(g) : "l"(&g_flags[grp * 32]) : "memory");
        } while (g < 32u * target);
    }
    __syncthreads();
}

// ---------------------------------------------------------------------------
// Init: zero h0 + reset group counters
// ---------------------------------------------------------------------------
__global__ void init_state_kernel() {
    int i = blockIdx.x * blockDim.x + threadIdx.x;
    if (i < BB * HH) {
        g_hhi[i] = __float2bfloat16(0.f);
        g_hlo[i] = __float2bfloat16(0.f);
    }
    if (i < 4 * 32) g_flags[i] = 0;
}

// ---------------------------------------------------------------------------
// conv_x: x[B][T][F] fp32 -> xhi/xlo bf16 rows m = t*B+b.
// ---------------------------------------------------------------------------
__global__ void conv_x_kernel(const float* __restrict__ x,
                              __nv_bfloat16* __restrict__ xhi,
                              __nv_bfloat16* __restrict__ xlo)
{
    const int gid = blockIdx.x * 256 + threadIdx.x;
    const int m = gid >> 5;
    const int c = (gid & 31) * 8;
    const int b = m & (BB - 1);
    const int t = m >> 8;
    const float* src = x + ((size_t)b * TT + t) * FF + c;
    float4 v0 = *(const float4*)src;
    float4 v1 = *(const float4*)(src + 4);
    float vv[8] = {v0.x, v0.y, v0.z, v0.w, v1.x, v1.y, v1.z, v1.w};
    __nv_bfloat16 hi8[8], lo8[8];
#pragma unroll
    for (int j = 0; j < 8; j++) split_bf16(vv[j], hi8[j], lo8[j]);
    *(uint4*)(xhi + (size_t)m * FF + c) = *(uint4*)hi8;
    *(uint4*)(xlo + (size_t)m * FF + c) = *(uint4*)lo8;
}

__global__ void conv_w_kernel(const float* __restrict__ W,
                              __nv_bfloat16* __restrict__ whi,
                              __nv_bfloat16* __restrict__ wlo)
{
    const int i = (blockIdx.x * 256 + threadIdx.x) * 4;
    float4 v = *(const float4*)(W + i);
    float vv[4] = {v.x, v.y, v.z, v.w};
    __nv_bfloat16 hi4[4], lo4[4];
#pragma unroll
    for (int j = 0; j < 4; j++) split_bf16(vv[j], hi4[j], lo4[j]);
    *(uint2*)(whi + i) = *(uint2*)hi4;
    *(uint2*)(wlo + i) = *(uint2*)lo4;
}

// ---------------------------------------------------------------------------
// bf16-split MMA GEMM (unchanged from R7): 128m x 64n, BK=32, 256 thr.
// ---------------------------------------------------------------------------
#define GA_STR 80
#define GB_STR 144
#define GS_AHI 0
#define GS_ALO (GS_AHI + 128 * GA_STR)
#define GS_BHI (GS_ALO + 128 * GA_STR)
#define GS_BLO (GS_BHI + 32 * GB_STR)
#define GS_TOT (GS_BLO + 32 * GB_STR)

__global__ void __launch_bounds__(256, 2)
gemm_bf16_kernel(const __nv_bfloat16* __restrict__ Ahi_g,
                 const __nv_bfloat16* __restrict__ Alo_g,
                 const __nv_bfloat16* __restrict__ Bhi_g,
                 const __nv_bfloat16* __restrict__ Blo_g,
                 const float* __restrict__ bias,
                 float* __restrict__ Cout)
{
    __shared__ char gsm[GS_TOT];
    const uint32_t sb = smem_u32(gsm);

    const int tid  = threadIdx.x;
    const int w    = tid >> 5;
    const int lane = tid & 31;
    const int n0 = blockIdx.x * 64;
    const int m0 = blockIdx.y * 128;
    const int wm = (w >> 1) * 32;
    const int wn = (w & 1) * 32;

    const int ar = tid >> 1;
    const int ac = (tid & 1) * 2;
    const size_t aoff = (size_t)(m0 + ar) * FF;
    const int br = tid >> 3;
    const int bc = tid & 7;

    uint4 pAh0 = *(const uint4*)(Ahi_g + aoff + (ac + 0) * 8);
    uint4 pAh1 = *(const uint4*)(Ahi_g + aoff + (ac + 1) * 8);
    uint4 pAl0 = *(const uint4*)(Alo_g + aoff + (ac + 0) * 8);
    uint4 pAl1 = *(const uint4*)(Alo_g + aoff + (ac + 1) * 8);
    uint4 pBh  = *(const uint4*)(Bhi_g + (size_t)br * GG + n0 + bc * 8);
    uint4 pBl  = *(const uint4*)(Blo_g + (size_t)br * GG + n0 + bc * 8);

    float acc[2][4][4];
#pragma unroll
    for (int mt = 0; mt < 2; mt++)
#pragma unroll
        for (int nt = 0; nt < 4; nt++)
#pragma unroll
            for (int q = 0; q < 4; q++) acc[mt][nt][q] = 0.f;

    const uint32_t aAddr = sb + GS_AHI + (wm + (lane & 15)) * GA_STR + (lane >> 4) * 16;
    const uint32_t bAddr = sb + GS_BHI + (lane & 15) * GB_STR + wn * 2;

    for (int kb = 0; kb < 8; kb++) {
        *(uint4*)(gsm + GS_AHI + ar * GA_STR + (ac + 0) * 16) = pAh0;
        *(uint4*)(gsm + GS_AHI + ar * GA_STR + (ac + 1) * 16) = pAh1;
        *(uint4*)(gsm + GS_ALO + ar * GA_STR + (ac + 0) * 16) = pAl0;
        *(uint4*)(gsm + GS_ALO + ar * GA_STR + (ac + 1) * 16) = pAl1;
        *(uint4*)(gsm + GS_BHI + br * GB_STR + bc * 16) = pBh;
        *(uint4*)(gsm + GS_BLO + br * GB_STR + bc * 16) = pBl;
        if (kb < 7) {
            const int k1 = (kb + 1) * 32;
            pAh0 = *(const uint4*)(Ahi_g + aoff + k1 + (ac + 0) * 8);
            pAh1 = *(const uint4*)(Ahi_g + aoff + k1 + (ac + 1) * 8);
            pAl0 = *(const uint4*)(Alo_g + aoff + k1 + (ac + 0) * 8);
            pAl1 = *(const uint4*)(Alo_g + aoff + k1 + (ac + 1) * 8);
            pBh  = *(const uint4*)(Bhi_g + (size_t)(k1 + br) * GG + n0 + bc * 8);
            pBl  = *(const uint4*)(Blo_g + (size_t)(k1 + br) * GG + n0 + bc * 8);
        }
        __syncthreads();

#pragma unroll
        for (int kc = 0; kc < 2; kc++) {
            uint32_t ah[2][4], al[2][4];
#pragma unroll
            for (int mt = 0; mt < 2; mt++) {
                const uint32_t a = aAddr + mt * 16 * GA_STR + kc * 32;
                ldmA(ah[mt][0], ah[mt][1], ah[mt][2], ah[mt][3], a);
                ldmA(al[mt][0], al[mt][1], al[mt][2], al[mt][3],
                     a + (GS_ALO - GS_AHI));
            }
            uint32_t bh[4][2], bl[4][2];
#pragma unroll
            for (int nt = 0; nt < 4; nt++) {
                const uint32_t b = bAddr + kc * 16 * GB_STR + nt * 16;
                ldmB(bh[nt][0], bh[nt][1], b);
                ldmB(bl[nt][0], bl[nt][1], b + (GS_BLO - GS_BHI));
            }
#pragma unroll
            for (int mt = 0; mt < 2; mt++)
#pragma unroll
                for (int nt = 0; nt < 4; nt++) {
                    mma_bf16(acc[mt][nt], ah[mt][0], ah[mt][1], ah[mt][2], ah[mt][3],
                             bh[nt][0], bh[nt][1]);
                    mma_bf16(acc[mt][nt], ah[mt][0], ah[mt][1], ah[mt][2], ah[mt][3],
                             bl[nt][0], bl[nt][1]);
                    mma_bf16(acc[mt][nt], al[mt][0], al[mt][1], al[mt][2], al[mt][3],
                             bh[nt][0], bh[nt][1]);
                }
        }
        __syncthreads();
    }

#pragma unroll
    for (int mt = 0; mt < 2; mt++) {
        const int mrow = m0 + wm + mt * 16 + (lane >> 2);
#pragma unroll
        for (int nt = 0; nt < 4; nt++) {
            const int n = n0 + wn + nt * 8 + (lane & 3) * 2;
            const float2 b2 = *(const float2*)(bias + n);
            float* o0 = Cout + (size_t)mrow * GG + n;
            float* o1 = Cout + (size_t)(mrow + 8) * GG + n;
            *(float2*)o0 = make_float2(acc[mt][nt][0] + b2.x, acc[mt][nt][1] + b2.y);
            *(float2*)o1 = make_float2(acc[mt][nt][2] + b2.x, acc[mt][nt][3] + b2.y);
        }
    }
}

// ---------------------------------------------------------------------------
// Persistent MMA LSTM layer, group-scoped sync + fragment-native epilogue.
// 128 CTAs x 256 thr. grp = bid>>5 (64 rows), hc0 = (bid&31)*8.
// Warps 0-3: gates (i,f), rows (w&3)*16; warps 4-7: gates (g,o), same rows.
// Only warps 4-7 spill z; pair syncs via named barrier; warps 0-3 epilogue.
// ---------------------------------------------------------------------------
#define SA_STRIDE 528
#define S_AHI 0
#define S_ALO (S_AHI + 64 * SA_STRIDE)
#define S_BHI (S_ALO + 64 * SA_STRIDE)
#define S_BLO (S_BHI + 4 * 256 * 16)
#define S_Z   (S_BLO + 4 * 256 * 16)
#define ZST2  18
#define S_TOT (S_Z + 64 * ZST2 * 4)

__global__ void __launch_bounds__(256, 1)
lstm_mma_kernel(const float* __restrict__ xw_all,       // [T][B][4H]
                const float* __restrict__ U,            // [H][4H]
                __nv_bfloat16* __restrict__ seqhi,      // [T*B][H] or null
                __nv_bfloat16* __restrict__ seqlo,
                float* __restrict__ hlast,              // [B][H]
                __nv_bfloat16* __restrict__ hhi,        // [2][B*H]
                __nv_bfloat16* __restrict__ hlo)
{
    extern __shared__ char smem[];
    const uint32_t sb = smem_u32(smem);
    float* zs = (float*)(smem + S_Z);

    const int tid  = threadIdx.x;
    const int w    = tid >> 5;
    const int lane = tid & 31;
    const int grp  = blockIdx.x >> 5;
    const int m0   = grp * 64;
    const int hc0  = (blockIdx.x & 31) * 8;
    const int wlow = w & 3;
    const int isEpi = (w < 4);

    // one-time: U gate slices -> smem bf16 hi/lo [gate][k][8cols]
    for (int i = tid; i < 4 * 256; i += 256) {
        const int g = i >> 8;
        const int k = i & 255;
        const float* up = U + (size_t)k * GG + g * HH + hc0;
        __nv_bfloat16 hi8[8], lo8[8];
#pragma unroll
        for (int j = 0; j < 8; j++) split_bf16(up[j], hi8[j], lo8[j]);
        *(uint4*)(smem + S_BHI + i * 16) = *(uint4*)hi8;
        *(uint4*)(smem + S_BLO + i * 16) = *(uint4*)lo8;
    }

    // fragment-native ownership (epilogue warps): rows r0, r0+8; cols c, c+1
    const int r0  = wlow * 16 + (lane >> 2);
    const int c   = (lane & 3) * 2;
    const int er0 = m0 + r0;
    const int er1 = er0 + 8;
    const int col = hc0 + c;

    float creg[4] = {0.f, 0.f, 0.f, 0.f};

    // prefetch xw(t=0): 4 gates x 2 rows x float2
    float2 xwf[2][4];
    if (isEpi) {
#pragma unroll
        for (int g = 0; g < 4; g++) {
            xwf[0][g] = *(const float2*)(xw_all + (size_t)er0 * GG + g * HH + col);
            xwf[1][g] = *(const float2*)(xw_all + (size_t)er1 * GG + g * HH + col);
        }
    }

    const int mbase = wlow * 16;
    const int ga = (w >> 2) * 2;    // warps 0-3: gates 0,1; warps 4-7: gates 2,3
    const uint32_t aAddrHi = sb + S_AHI + (mbase + (lane & 15)) * SA_STRIDE
                            + (lane >> 4) * 16;
    const uint32_t aAddrLo = aAddrHi + (S_ALO - S_AHI);
    const uint32_t bAddrHi0 = sb + S_BHI + (ga + 0) * 4096 + (lane & 15) * 16;
    const uint32_t bAddrHi1 = sb + S_BHI + (ga + 1) * 4096 + (lane & 15) * 16;
    const uint32_t bAddrLo0 = bAddrHi0 + (S_BLO - S_BHI);
    const uint32_t bAddrLo1 = bAddrHi1 + (S_BLO - S_BHI);

    for (int t = 0; t < TT; t++) {
        grp_wait(grp, (unsigned)t);
        const int ph = t & 1;
        const __nv_bfloat16* shi = hhi + (size_t)ph * BB * HH;
        const __nv_bfloat16* slo = hlo + (size_t)ph * BB * HH;

        // stage h rows m0..m0+63 -> A_hi/A_lo smem
#pragma unroll
        for (int i = 0; i < 8; i++) {
            const int id = tid + i * 256;
            const int r  = id >> 5;
            const int cc = id & 31;
            const uint4 vh = *((const uint4*)(shi + (size_t)(m0 + r) * HH) + cc);
            const uint4 vl = *((const uint4*)(slo + (size_t)(m0 + r) * HH) + cc);
            *(uint4*)(smem + S_AHI + r * SA_STRIDE + cc * 16) = vh;
            *(uint4*)(smem + S_ALO + r * SA_STRIDE + cc * 16) = vl;
        }
        __syncthreads();

        float d[2][3][4];
#pragma unroll
        for (int gt = 0; gt < 2; gt++)
#pragma unroll
            for (int s = 0; s < 3; s++)
#pragma unroll
                for (int q = 0; q < 4; q++) d[gt][s][q] = 0.f;

#pragma unroll
        for (int kc = 0; kc < 16; kc++) {
            uint32_t ah0, ah1, ah2, ah3, al0, al1, al2, al3;
            ldmA(ah0, ah1, ah2, ah3, aAddrHi + kc * 32);
            ldmA(al0, al1, al2, al3, aAddrLo + kc * 32);
            uint32_t bh00, bh01, bl00, bl01, bh10, bh11, bl10, bl11;
            ldmB(bh00, bh01, bAddrHi0 + kc * 256);
            ldmB(bl00, bl01, bAddrLo0 + kc * 256);
            ldmB(bh10, bh11, bAddrHi1 + kc * 256);
            ldmB(bl10, bl11, bAddrLo1 + kc * 256);
            mma_bf16(d[0][0], ah0, ah1, ah2, ah3, bh00, bh01);
            mma_bf16(d[0][1], ah0, ah1, ah2, ah3, bl00, bl01);
            mma_bf16(d[0][2], al0, al1, al2, al3, bh00, bh01);
            mma_bf16(d[1][0], ah0, ah1, ah2, ah3, bh10, bh11);
            mma_bf16(d[1][1], ah0, ah1, ah2, ah3, bl10, bl11);
            mma_bf16(d[1][2], al0, al1, al2, al3, bh10, bh11);
        }

        // sum split terms
        float v[2][4];
#pragma unroll
        for (int gt = 0; gt < 2; gt++)
#pragma unroll
            for (int q = 0; q < 4; q++)
                v[gt][q] = d[gt][0][q] + d[gt][1][q] + d[gt][2][q];

        // warps 4-7 (gates g,o) spill to smem
        if (!isEpi) {
            *(float2*)&zs[r0 * ZST2 + 0 + c]       = make_float2(v[0][0], v[0][1]);
            *(float2*)&zs[(r0 + 8) * ZST2 + 0 + c] = make_float2(v[0][2], v[0][3]);
            *(float2*)&zs[r0 * ZST2 + 8 + c]       = make_float2(v[1][0], v[1][1]);
            *(float2*)&zs[(r0 + 8) * ZST2 + 8 + c] = make_float2(v[1][2], v[1][3]);
        }
        asm volatile("bar.sync %0, 64;" :: "r"(1 + wlow) : "memory");

        if (isEpi) {
            // my regs: v[0] = zi, v[1] = zf; partner smem: zg, zo
            const float2 zg0 = *(float2*)&zs[r0 * ZST2 + 0 + c];
            const float2 zg1 = *(float2*)&zs[(r0 + 8) * ZST2 + 0 + c];
            const float2 zo0 = *(float2*)&zs[r0 * ZST2 + 8 + c];
            const float2 zo1 = *(float2*)&zs[(r0 + 8) * ZST2 + 8 + c];

            float zg[4] = {zg0.x, zg0.y, zg1.x, zg1.y};
            float zo[4] = {zo0.x, zo0.y, zo1.x, zo1.y};
            float hv[4];
#pragma unroll
            for (int q = 0; q < 4; q++) {
                const int rr = q >> 1;          // row half
                const int cc2 = q & 1;          // col within pair
                const float zif = v[0][q] + ((const float*)&xwf[rr][0])[cc2];
                const float zff = v[1][q] + ((const float*)&xwf[rr][1])[cc2];
                const float zgf = zg[q]   + ((const float*)&xwf[rr][2])[cc2];
                const float zof = zo[q]   + ((const float*)&xwf[rr][3])[cc2];
                const float ig = sigf(zif), fg = sigf(zff);
                const float gg = __tanhf(zgf), og = sigf(zof);
                const float cn = fg * creg[q] + ig * gg;
                creg[q] = cn;
                hv[q] = og * __tanhf(cn);
            }

            // pack h -> bf16 hi/lo (2 cols per row)
            __nv_bfloat16 hH[4], hL[4];
#pragma unroll
            for (int q = 0; q < 4; q++) split_bf16(hv[q], hH[q], hL[q]);
            const uint32_t phi0 = (uint32_t)__bfloat16_as_ushort(hH[0])
                                | ((uint32_t)__bfloat16_as_ushort(hH[1]) << 16);
            const uint32_t plo0 = (uint32_t)__bfloat16_as_ushort(hL[0])
                                | ((uint32_t)__bfloat16_as_ushort(hL[1]) << 16);
            const uint32_t phi1 = (uint32_t)__bfloat16_as_ushort(hH[2])
                                | ((uint32_t)__bfloat16_as_ushort(hH[3]) << 16);
            const uint32_t plo1 = (uint32_t)__bfloat16_as_ushort(hL[2])
                                | ((uint32_t)__bfloat16_as_ushort(hL[3]) << 16);

            const int np = ph ^ 1;
            const size_t base = (size_t)np * BB * HH;
            *(uint32_t*)(hhi + base + (size_t)er0 * HH + col) = phi0;
            *(uint32_t*)(hlo + base + (size_t)er0 * HH + col) = plo0;
            *(uint32_t*)(hhi + base + (size_t)er1 * HH + col) = phi1;
            *(uint32_t*)(hlo + base + (size_t)er1 * HH + col) = plo1;

            if (seqhi) {
                const size_t s0 = ((size_t)t * BB + er0) * HH + col;
                const size_t s1 = ((size_t)t * BB + er1) * HH + col;
                *(uint32_t*)(seqhi + s0) = phi0;
                *(uint32_t*)(seqlo + s0) = plo0;
                *(uint32_t*)(seqhi + s1) = phi1;
                *(uint32_t*)(seqlo + s1) = plo1;
            } else if (t == TT - 1) {
                *(float2*)(hlast + (size_t)er0 * HH + col) = make_float2(hv[0], hv[1]);
                *(float2*)(hlast + (size_t)er1 * HH + col) = make_float2(hv[2], hv[3]);
            }
        }

        grp_arrive(grp);

        // prefetch next xw while group-mates finish
        if (isEpi && t + 1 < TT) {
            const float* xr0 = xw_all + ((size_t)(t + 1) * BB + er0) * GG;
            const float* xr1 = xw_all + ((size_t)(t + 1) * BB + er1) * GG;
#pragma unroll
            for (int g = 0; g < 4; g++) {
                xwf[0][g] = *(const float2*)(xr0 + g * HH + col);
                xwf[1][g] = *(const float2*)(xr1 + g * HH + col);
            }
        }
    }
}

// ---------------------------------------------------------------------------
// out[b] = sum_k hlast[b][k] * Wd[k] + bd[0]
// ---------------------------------------------------------------------------
__global__ void dense_out_kernel(const float* __restrict__ hlast,
                                 const float* __restrict__ Wd,
                                 const float* __restrict__ bd,
                                 float* __restrict__ out)
{
    __shared__ float red[256];
    const int b = blockIdx.x;
    const int k = threadIdx.x;
    red[k] = hlast[b * HH + k] * Wd[k];
    __syncthreads();
    for (int s = 128; s > 0; s >>= 1) {
        if (k < s) red[k] += red[k + s];
        __syncthreads();
    }
    if (k == 0) out[b] = red[0] + bd[0];
}

// ---------------------------------------------------------------------------
// Launch
// ---------------------------------------------------------------------------
extern "C" void kernel_launch(void* const* d_in, const int* in_sizes, int n_in,
                              void* d_out, int out_size)
{
    const float* x  = (const float*)d_in[0];
    const float* W1 = (const float*)d_in[1];
    const float* U1 = (const float*)d_in[2];
    const float* b1 = (const float*)d_in[3];
    const float* W2 = (const float*)d_in[4];
    const float* U2 = (const float*)d_in[5];
    const float* b2 = (const float*)d_in[6];
    const float* Wd = (const float*)d_in[7];
    const float* bd = (const float*)d_in[8];
    float* out = (float*)d_out;

    float *xw, *hlast;
    __nv_bfloat16 *xhi, *xlo, *h1hi, *h1lo, *whi, *wlo, *hhi, *hlo;
    cudaGetSymbolAddress((void**)&xw, g_xw);
    cudaGetSymbolAddress((void**)&xhi, g_xhi);
    cudaGetSymbolAddress((void**)&xlo, g_xlo);
    cudaGetSymbolAddress((void**)&h1hi, g_h1hi);
    cudaGetSymbolAddress((void**)&h1lo, g_h1lo);
    cudaGetSymbolAddress((void**)&whi, g_whi);
    cudaGetSymbolAddress((void**)&wlo, g_wlo);
    cudaGetSymbolAddress((void**)&hlast, g_hlast);
    cudaGetSymbolAddress((void**)&hhi, g_hhi);
    cudaGetSymbolAddress((void**)&hlo, g_hlo);

    cudaFuncSetAttribute(lstm_mma_kernel,
                         cudaFuncAttributeMaxDynamicSharedMemorySize, S_TOT);

    const dim3 gemm_grid(GG / 64, MM / 128);

    // Layer 1
    conv_x_kernel<<<MM * 32 / 256, 256>>>(x, xhi, xlo);
    conv_w_kernel<<<FF * GG / 4 / 256, 256>>>(W1, whi, wlo);
    gemm_bf16_kernel<<<gemm_grid, 256>>>(xhi, xlo, whi, wlo, b1, xw);
    init_state_kernel<<<(BB * HH + 255) / 256, 256>>>();
    lstm_mma_kernel<<<NB, 256, S_TOT>>>(xw, U1, h1hi, h1lo, hlast, hhi, hlo);

    // Layer 2
    conv_w_kernel<<<FF * GG / 4 / 256, 256>>>(W2, whi, wlo);
    gemm_bf16_kernel<<<gemm_grid, 256>>>(h1hi, h1lo, whi, wlo, b2, xw);
    init_state_kernel<<<(BB * HH + 255) / 256, 256>>>();
    lstm_mma_kernel<<<NB, 256, S_TOT>>>(xw, U2, (__nv_bfloat16*)0,
                                        (__nv_bfloat16*)0, hlast, hhi, hlo);

    dense_out_kernel<<<BB, 256>>>(hlast, Wd, bd, out);
}

// round 9
// speedup vs baseline: 3.3048x; 1.1215x over previous
#include <cuda_runtime.h>
#include <cuda_bf16.h>
#include <math.h>
#include <stdint.h>

#define BB 256
#define TT 512
#define FF 256
#define HH 256
#define GG 1024
#define MM (TT * BB)

// ---------------- device globals (no runtime allocation) --------------------
__device__ __nv_bfloat16 g_xhi[(size_t)MM * FF];    // 64 MB, row m = t*B+b
__device__ __nv_bfloat16 g_xlo[(size_t)MM * FF];
__device__ __nv_bfloat16 g_h1hi[(size_t)MM * HH];   // layer-1 h sequence
__device__ __nv_bfloat16 g_h1lo[(size_t)MM * HH];
__device__ __nv_bfloat16 g_h2hi[2 * BB * HH];       // layer-2 h double buffer
__device__ __nv_bfloat16 g_h2lo[2 * BB * HH];
__device__ float g_hlast[BB * HH];
__device__ unsigned g_flags[8 * 32];                 // [layer*4+grp]*32

// ---------------- helpers ----------------------------------------------------
__device__ __forceinline__ float sigf(float v) { return 1.0f / (1.0f + __expf(-v)); }

__device__ __forceinline__ uint32_t smem_u32(const void* p) {
    uint32_t a;
    asm("{ .reg .u64 t; cvta.to.shared.u64 t, %1; cvt.u32.u64 %0, t; }"
        : "=r"(a) : "l"(p));
    return a;
}
__device__ __forceinline__ void ldmA(uint32_t& a0, uint32_t& a1,
                                     uint32_t& a2, uint32_t& a3, uint32_t addr) {
    asm volatile("ldmatrix.sync.aligned.m8n8.x4.shared.b16 {%0,%1,%2,%3}, [%4];"
                 : "=r"(a0), "=r"(a1), "=r"(a2), "=r"(a3) : "r"(addr));
}
__device__ __forceinline__ void ldmB(uint32_t& b0, uint32_t& b1, uint32_t addr) {
    asm volatile("ldmatrix.sync.aligned.m8n8.x2.trans.shared.b16 {%0,%1}, [%2];"
                 : "=r"(b0), "=r"(b1) : "r"(addr));
}
__device__ __forceinline__ void mma_bf16(float* d, uint32_t a0, uint32_t a1,
                                         uint32_t a2, uint32_t a3,
                                         uint32_t b0, uint32_t b1) {
    asm volatile(
        "mma.sync.aligned.m16n8k16.row.col.f32.bf16.bf16.f32 "
        "{%0,%1,%2,%3}, {%4,%5,%6,%7}, {%8,%9}, {%0,%1,%2,%3};"
        : "+f"(d[0]), "+f"(d[1]), "+f"(d[2]), "+f"(d[3])
        : "r"(a0), "r"(a1), "r"(a2), "r"(a3), "r"(b0), "r"(b1));
}
__device__ __forceinline__ void split_bf16(float v, __nv_bfloat16& hi, __nv_bfloat16& lo) {
    hi = __float2bfloat16_rn(v);
    lo = __float2bfloat16_rn(v - __bfloat162float(hi));
}
__device__ __forceinline__ void pollFlag(unsigned* f, unsigned target) {
    unsigned g;
    do {
        asm volatile("ld.acquire.gpu.u32 %0, [%1];" : "=r"(g) : "l"(f) : "memory");
    } while (g < target);
}
__device__ __forceinline__ void addFlag(unsigned* f) {
    unsigned old;
    asm volatile("atom.add.release.gpu.u32 %0, [%1], 1;"
                 : "=r"(old) : "l"(f) : "memory");
}

// ---------------------------------------------------------------------------
// init: reset flags only (h(-1) handled by skipping pass-2 at t=0)
// ---------------------------------------------------------------------------
__global__ void init_flags_kernel() {
    if (threadIdx.x < 8 * 32) g_flags[threadIdx.x] = 0;
}

// ---------------------------------------------------------------------------
// conv_x: x[B][T][F] fp32 -> xhi/xlo bf16 rows m = t*B+b.
// ---------------------------------------------------------------------------
__global__ void conv_x_kernel(const float* __restrict__ x,
                              __nv_bfloat16* __restrict__ xhi,
                              __nv_bfloat16* __restrict__ xlo)
{
    const int gid = blockIdx.x * 256 + threadIdx.x;
    const int m = gid >> 5;
    const int c = (gid & 31) * 8;
    const int b = m & (BB - 1);
    const int t = m >> 8;
    const float* src = x + ((size_t)b * TT + t) * FF + c;
    float4 v0 = *(const float4*)src;
    float4 v1 = *(const float4*)(src + 4);
    float vv[8] = {v0.x, v0.y, v0.z, v0.w, v1.x, v1.y, v1.z, v1.w};
    __nv_bfloat16 hi8[8], lo8[8];
#pragma unroll
    for (int j = 0; j < 8; j++) split_bf16(vv[j], hi8[j], lo8[j]);
    *(uint4*)(xhi + (size_t)m * FF + c) = *(uint4*)hi8;
    *(uint4*)(xlo + (size_t)m * FF + c) = *(uint4*)lo8;
}

// ---------------------------------------------------------------------------
// Fused 2-layer pipelined LSTM. 128 CTAs x 256 thr.
// bid<64: layer 1 (4 grps x 16 CTAs); bid>=64: layer 2 (same).
// CTA tile: 64 batch rows x (4 gates x 16 hc). Per step:
//   pass 1: A1 @ Wslice  (A1 = x(t) for L1, h1(t) for L2)  [no recurrence]
//   pass 2: h(t-1) @ Uslice  (skipped at t=0)
// Both bf16 hi/lo split (3 MMA terms), fp32 accum. c in regs all 512 steps.
// L2 group g waits on L1 group g's counter (1-step pipeline lag).
// ---------------------------------------------------------------------------
#define SA_STR 528
#define S_AHI 0
#define S_ALO 33792
#define S_BWH 67584
#define S_BWL 100352
#define S_BUH 133120
#define S_BUL 165888
#define S_Z   198656
#define ZST   36
#define S_TOT (S_Z + 64 * ZST * 4)    /* 207872 */

__device__ __forceinline__ void mma_pass(float acc[2][2][3][4],
                                         uint32_t aHi, uint32_t aLo,
                                         uint32_t bBase, uint32_t bLoOff)
{
#pragma unroll
    for (int kc = 0; kc < 16; kc++) {
        uint32_t ah0, ah1, ah2, ah3, al0, al1, al2, al3;
        ldmA(ah0, ah1, ah2, ah3, aHi + kc * 32);
        ldmA(al0, al1, al2, al3, aLo + kc * 32);
#pragma unroll
        for (int gl = 0; gl < 2; gl++) {
#pragma unroll
            for (int j = 0; j < 2; j++) {
                const uint32_t b = bBase + gl * 8192 + j * 16 + kc * 512;
                uint32_t bh0, bh1, bl0, bl1;
                ldmB(bh0, bh1, b);
                ldmB(bl0, bl1, b + bLoOff);
                mma_bf16(acc[gl][j][0], ah0, ah1, ah2, ah3, bh0, bh1);
                mma_bf16(acc[gl][j][1], ah0, ah1, ah2, ah3, bl0, bl1);
                mma_bf16(acc[gl][j][2], al0, al1, al2, al3, bh0, bh1);
            }
        }
    }
}

__global__ void __launch_bounds__(256, 1)
fused_lstm_kernel(const __nv_bfloat16* __restrict__ xhi,
                  const __nv_bfloat16* __restrict__ xlo,
                  const float* __restrict__ W1, const float* __restrict__ U1,
                  const float* __restrict__ b1,
                  const float* __restrict__ W2, const float* __restrict__ U2,
                  const float* __restrict__ b2,
                  __nv_bfloat16* __restrict__ h1hi,
                  __nv_bfloat16* __restrict__ h1lo,
                  __nv_bfloat16* __restrict__ h2hi,
                  __nv_bfloat16* __restrict__ h2lo,
                  float* __restrict__ hlast)
{
    extern __shared__ char smem[];
    const uint32_t sb = smem_u32(smem);
    float* zs = (float*)(smem + S_Z);

    const int tid  = threadIdx.x;
    const int w    = tid >> 5;
    const int lane = tid & 31;
    const int layer = blockIdx.x >> 6;
    const int sub   = blockIdx.x & 63;
    const int grp   = sub >> 4;
    const int gm0   = grp * 64;
    const int hc0   = (sub & 15) * 16;
    const int msub  = w & 3;
    const int gp    = w >> 2;         // 0: gates i,f (epilogue); 1: gates g,o (spill)
    const int isEpi = (gp == 0);

    const float* Wsrc = layer ? W2 : W1;
    const float* Usrc = layer ? U2 : U1;
    const float* bsrc = layer ? b2 : b1;
    unsigned* ownFlag = &g_flags[(layer * 4 + grp) * 32];
    unsigned* l1Flag  = &g_flags[grp * 32];

    // ---- one-time: fill B smem (W and U slices) as bf16 hi/lo -------------
    // layout: [gate][k][16 hc], 32B per (gate,k) row
    for (int i = tid; i < 4 * 256 * 2; i += 256) {
        const int g = i >> 9;
        const int k = (i >> 1) & 255;
        const int half = i & 1;
        const int co = g * HH + hc0 + half * 8;
        const uint32_t so = (uint32_t)(g * 8192 + k * 32 + half * 16);
        {
            const float* src = Wsrc + (size_t)k * GG + co;
            __nv_bfloat16 h8[8], l8[8];
#pragma unroll
            for (int j = 0; j < 8; j++) split_bf16(src[j], h8[j], l8[j]);
            *(uint4*)(smem + S_BWH + so) = *(uint4*)h8;
            *(uint4*)(smem + S_BWL + so) = *(uint4*)l8;
        }
        {
            const float* src = Usrc + (size_t)k * GG + co;
            __nv_bfloat16 h8[8], l8[8];
#pragma unroll
            for (int j = 0; j < 8; j++) split_bf16(src[j], h8[j], l8[j]);
            *(uint4*)(smem + S_BUH + so) = *(uint4*)h8;
            *(uint4*)(smem + S_BUL + so) = *(uint4*)l8;
        }
    }

    // fragment-native ownership (epilogue warps)
    const int r0 = msub * 16 + (lane >> 2);
    const int c  = (lane & 3) * 2;
    float biaf[4][2][2];
    if (isEpi) {
#pragma unroll
        for (int g = 0; g < 4; g++)
#pragma unroll
            for (int j = 0; j < 2; j++) {
                const float2 bb = *(const float2*)(bsrc + g * HH + hc0 + j * 8 + c);
                biaf[g][j][0] = bb.x;
                biaf[g][j][1] = bb.y;
            }
    }
    float creg[8];
#pragma unroll
    for (int i = 0; i < 8; i++) creg[i] = 0.f;

    const uint32_t aHi = sb + S_AHI + (msub * 16 + (lane & 15)) * SA_STR
                        + (lane >> 4) * 16;
    const uint32_t aLo = aHi + (S_ALO - S_AHI);
    const uint32_t bW  = sb + S_BWH + gp * 2 * 8192 + (lane & 15) * 32;
    const uint32_t bU  = sb + S_BUH + gp * 2 * 8192 + (lane & 15) * 32;
    const uint32_t bLoOff = S_BWL - S_BWH;   // 32768, same for BU

    for (int t = 0; t < TT; t++) {
        // ---- stage pass-1 A operand ----
        if (layer == 0) {
            const size_t rowb = (size_t)t * BB + gm0;
#pragma unroll
            for (int i = 0; i < 8; i++) {
                const int id = tid + i * 256;
                const int r  = id >> 5;
                const int cc = id & 31;
                const uint4 vh = *((const uint4*)(xhi + (rowb + r) * FF) + cc);
                const uint4 vl = *((const uint4*)(xlo + (rowb + r) * FF) + cc);
                *(uint4*)(smem + S_AHI + r * SA_STR + cc * 16) = vh;
                *(uint4*)(smem + S_ALO + r * SA_STR + cc * 16) = vl;
            }
        } else {
            if (tid == 0) pollFlag(l1Flag, 16u * (unsigned)(t + 1));
            __syncthreads();
            const size_t rowb = (size_t)t * BB + gm0;
#pragma unroll
            for (int i = 0; i < 8; i++) {
                const int id = tid + i * 256;
                const int r  = id >> 5;
                const int cc = id & 31;
                const uint4 vh = *((const uint4*)(h1hi + (rowb + r) * HH) + cc);
                const uint4 vl = *((const uint4*)(h1lo + (rowb + r) * HH) + cc);
                *(uint4*)(smem + S_AHI + r * SA_STR + cc * 16) = vh;
                *(uint4*)(smem + S_ALO + r * SA_STR + cc * 16) = vl;
            }
        }
        __syncthreads();

        float acc[2][2][3][4];
#pragma unroll
        for (int gl = 0; gl < 2; gl++)
#pragma unroll
            for (int j = 0; j < 2; j++)
#pragma unroll
                for (int s = 0; s < 3; s++)
#pragma unroll
                    for (int q = 0; q < 4; q++) acc[gl][j][s][q] = 0.f;

        // pass 1: A1 @ W-slice
        mma_pass(acc, aHi, aLo, bW, bLoOff);

        // wait for own recurrent state, then pass 2
        if (t > 0) {
            if (tid == 0) pollFlag(ownFlag, 16u * (unsigned)t);
        }
        __syncthreads();   // also: all pass-1 reads of A done
        if (t > 0) {
            if (layer == 0) {
                const size_t rowb = (size_t)(t - 1) * BB + gm0;
#pragma unroll
                for (int i = 0; i < 8; i++) {
                    const int id = tid + i * 256;
                    const int r  = id >> 5;
                    const int cc = id & 31;
                    const uint4 vh = *((const uint4*)(h1hi + (rowb + r) * HH) + cc);
                    const uint4 vl = *((const uint4*)(h1lo + (rowb + r) * HH) + cc);
                    *(uint4*)(smem + S_AHI + r * SA_STR + cc * 16) = vh;
                    *(uint4*)(smem + S_ALO + r * SA_STR + cc * 16) = vl;
                }
            } else {
                const int ph = t & 1;
                const __nv_bfloat16* shi = h2hi + (size_t)ph * BB * HH;
                const __nv_bfloat16* slo = h2lo + (size_t)ph * BB * HH;
#pragma unroll
                for (int i = 0; i < 8; i++) {
                    const int id = tid + i * 256;
                    const int r  = id >> 5;
                    const int cc = id & 31;
                    const uint4 vh = *((const uint4*)(shi + (size_t)(gm0 + r) * HH) + cc);
                    const uint4 vl = *((const uint4*)(slo + (size_t)(gm0 + r) * HH) + cc);
                    *(uint4*)(smem + S_AHI + r * SA_STR + cc * 16) = vh;
                    *(uint4*)(smem + S_ALO + r * SA_STR + cc * 16) = vl;
                }
            }
            __syncthreads();
            mma_pass(acc, aHi, aLo, bU, bLoOff);
        }

        // ---- epilogue ----
        float v[2][2][4];
#pragma unroll
        for (int gl = 0; gl < 2; gl++)
#pragma unroll
            for (int j = 0; j < 2; j++)
#pragma unroll
                for (int q = 0; q < 4; q++)
                    v[gl][j][q] = acc[gl][j][0][q] + acc[gl][j][1][q] + acc[gl][j][2][q];

        if (!isEpi) {
            // gates g,o -> smem
#pragma unroll
            for (int gl = 0; gl < 2; gl++)
#pragma unroll
                for (int j = 0; j < 2; j++) {
                    *(float2*)&zs[r0 * ZST + gl * 16 + j * 8 + c] =
                        make_float2(v[gl][j][0], v[gl][j][1]);
                    *(float2*)&zs[(r0 + 8) * ZST + gl * 16 + j * 8 + c] =
                        make_float2(v[gl][j][2], v[gl][j][3]);
                }
        }
        asm volatile("bar.sync %0, 64;" :: "r"(1 + msub) : "memory");

        if (isEpi) {
            float zgv[2][2][2], zov[2][2][2];  // [j][rh][cp]
#pragma unroll
            for (int j = 0; j < 2; j++)
#pragma unroll
                for (int rh = 0; rh < 2; rh++) {
                    const float2 a = *(float2*)&zs[(r0 + rh * 8) * ZST + 0 + j * 8 + c];
                    const float2 b = *(float2*)&zs[(r0 + rh * 8) * ZST + 16 + j * 8 + c];
                    zgv[j][rh][0] = a.x; zgv[j][rh][1] = a.y;
                    zov[j][rh][0] = b.x; zov[j][rh][1] = b.y;
                }

            float hv[2][2][2];  // [rh][j][cp]
#pragma unroll
            for (int rh = 0; rh < 2; rh++)
#pragma unroll
                for (int j = 0; j < 2; j++)
#pragma unroll
                    for (int cp = 0; cp < 2; cp++) {
                        const int q = rh * 2 + cp;
                        const float zi = v[0][j][q]     + biaf[0][j][cp];
                        const float zf = v[1][j][q]     + biaf[1][j][cp];
                        const float zg = zgv[j][rh][cp] + biaf[2][j][cp];
                        const float zo = zov[j][rh][cp] + biaf[3][j][cp];
                        const float ig = sigf(zi), fg = sigf(zf);
                        const float gg = __tanhf(zg), og = sigf(zo);
                        const int ci = rh * 4 + j * 2 + cp;
                        const float cn = fg * creg[ci] + ig * gg;
                        creg[ci] = cn;
                        hv[rh][j][cp] = og * __tanhf(cn);
                    }

            const int np = (t & 1) ^ 1;
#pragma unroll
            for (int rh = 0; rh < 2; rh++) {
                const int row = gm0 + r0 + rh * 8;
#pragma unroll
                for (int j = 0; j < 2; j++) {
                    const int colb = hc0 + j * 8 + c;
                    __nv_bfloat16 h0h, h1h, h0l, h1l;
                    split_bf16(hv[rh][j][0], h0h, h0l);
                    split_bf16(hv[rh][j][1], h1h, h1l);
                    const uint32_t phi = (uint32_t)__bfloat16_as_ushort(h0h)
                                       | ((uint32_t)__bfloat16_as_ushort(h1h) << 16);
                    const uint32_t plo = (uint32_t)__bfloat16_as_ushort(h0l)
                                       | ((uint32_t)__bfloat16_as_ushort(h1l) << 16);
                    if (layer == 0) {
                        const size_t off = ((size_t)t * BB + row) * HH + colb;
                        *(uint32_t*)(h1hi + off) = phi;
                        *(uint32_t*)(h1lo + off) = plo;
                    } else {
                        const size_t off = (size_t)np * BB * HH
                                         + (size_t)row * HH + colb;
                        *(uint32_t*)(h2hi + off) = phi;
                        *(uint32_t*)(h2lo + off) = plo;
                        if (t == TT - 1)
                            *(float2*)(hlast + (size_t)row * HH + colb) =
                                make_float2(hv[rh][j][0], hv[rh][j][1]);
                    }
                }
            }
        }

        // arrive: all step-t work (incl. h writes) done for this CTA
        __syncthreads();
        if (tid == 0) addFlag(ownFlag);
    }
}

// ---------------------------------------------------------------------------
// out[b] = sum_k hlast[b][k] * Wd[k] + bd[0]
// ---------------------------------------------------------------------------
__global__ void dense_out_kernel(const float* __restrict__ hlast,
                                 const float* __restrict__ Wd,
                                 const float* __restrict__ bd,
                                 float* __restrict__ out)
{
    __shared__ float red[256];
    const int b = blockIdx.x;
    const int k = threadIdx.x;
    red[k] = hlast[b * HH + k] * Wd[k];
    __syncthreads();
    for (int s = 128; s > 0; s >>= 1) {
        if (k < s) red[k] += red[k + s];
        __syncthreads();
    }
    if (k == 0) out[b] = red[0] + bd[0];
}

// ---------------------------------------------------------------------------
// Launch: 4 graph nodes.
// ---------------------------------------------------------------------------
extern "C" void kernel_launch(void* const* d_in, const int* in_sizes, int n_in,
                              void* d_out, int out_size)
{
    const float* x  = (const float*)d_in[0];
    const float* W1 = (const float*)d_in[1];
    const float* U1 = (const float*)d_in[2];
    const float* b1 = (const float*)d_in[3];
    const float* W2 = (const float*)d_in[4];
    const float* U2 = (const float*)d_in[5];
    const float* b2 = (const float*)d_in[6];
    const float* Wd = (const float*)d_in[7];
    const float* bd = (const float*)d_in[8];
    float* out = (float*)d_out;

    float* hlast;
    __nv_bfloat16 *xhi, *xlo, *h1hi, *h1lo, *h2hi, *h2lo;
    cudaGetSymbolAddress((void**)&xhi, g_xhi);
    cudaGetSymbolAddress((void**)&xlo, g_xlo);
    cudaGetSymbolAddress((void**)&h1hi, g_h1hi);
    cudaGetSymbolAddress((void**)&h1lo, g_h1lo);
    cudaGetSymbolAddress((void**)&h2hi, g_h2hi);
    cudaGetSymbolAddress((void**)&h2lo, g_h2lo);
    cudaGetSymbolAddress((void**)&hlast, g_hlast);

    cudaFuncSetAttribute(fused_lstm_kernel,
                         cudaFuncAttributeMaxDynamicSharedMemorySize, S_TOT);

    conv_x_kernel<<<MM * 32 / 256, 256>>>(x, xhi, xlo);
    init_flags_kernel<<<1, 256>>>();
    fused_lstm_kernel<<<128, 256, S_TOT>>>(xhi, xlo, W1, U1, b1, W2, U2, b2,
                                           h1hi, h1lo, h2hi, h2lo, hlast);
    dense_out_kernel<<<BB, 256>>>(hlast, Wd, bd, out);
}